// round 6
// baseline (speedup 1.0000x reference)
#include <cuda_runtime.h>
#include <cuda_bf16.h>
#include <cstdint>

#define NN 100000
#define EE 1600000
#define RR 8
#define DD 128
#define MBINS (RR * NN)   // sort bins, key = r*NN + dst

// ---------------------------------------------------------------------------
// Scratch (device globals; no allocation allowed anywhere).
// ---------------------------------------------------------------------------
__device__ __align__(16) float g_xr[(size_t)NN * DD];
__device__ __align__(16) float g_h [(size_t)NN * DD];
__device__ __align__(16) __nv_bfloat16 g_ah[(size_t)NN * DD];
__device__ __align__(16) __nv_bfloat16 g_al[(size_t)NN * DD];
__device__ __align__(16) __nv_bfloat16 g_wh[9 * DD * DD];
__device__ __align__(16) __nv_bfloat16 g_wl[9 * DD * DD];
__device__ int g_cnt[MBINS];     // per-(rel,dst) edge counts
__device__ int g_off[MBINS];     // exclusive offsets (kept intact)
__device__ int g_cur[MBINS];     // scatter cursors (destroyed)
__device__ int g_bsum[1024];     // block partials for the scan
__device__ int g_src[EE];        // src node ids, sorted by (rel,dst)
__device__ int g_shift;          // 1 if edge arrays are int64, 0 if int32

// ---------------------------------------------------------------------------
// dtype autodetect (int64 edges => all odd 32-bit words zero)
// ---------------------------------------------------------------------------
__global__ void detect_k(const int* __restrict__ et, int E) {
    __shared__ int any;
    if (threadIdx.x == 0) any = 0;
    __syncthreads();
    int n = min(E, 4096);
    int local = 0;
    for (int i = threadIdx.x; i < n; i += blockDim.x) local |= et[2 * i + 1];
    if (local) atomicOr(&any, 1);
    __syncthreads();
    if (threadIdx.x == 0) g_shift = any ? 0 : 1;
}

// ---------------------------------------------------------------------------
// Counting sort by key (rel, dst)
// ---------------------------------------------------------------------------
__global__ void zero_cnt_k(int* cnt, int n) {
    int i = blockIdx.x * blockDim.x + threadIdx.x;
    if (i < n) cnt[i] = 0;
}
__global__ void count_k(const int* __restrict__ ei, const int* __restrict__ et,
                        int* __restrict__ cnt, int E) {
    int e = blockIdx.x * blockDim.x + threadIdx.x;
    if (e < E) {
        const int sh = g_shift;
        int d = ei[(E << sh) + (e << sh)];
        int r = et[e << sh];
        if ((unsigned)d < NN && (unsigned)r < RR)
            atomicAdd(&cnt[r * NN + d], 1);
    }
}
// Pass 1: per-1024-chunk exclusive scan + block totals
__global__ void scan1_k(const int* __restrict__ cnt, int* __restrict__ off,
                        int* __restrict__ bsum, int M) {
    __shared__ int wsum[8];
    const int t = threadIdx.x;
    const int base = blockIdx.x * 1024 + t * 4;
    int v0 = 0, v1 = 0, v2 = 0, v3 = 0;
    if (base + 0 < M) v0 = cnt[base + 0];
    if (base + 1 < M) v1 = cnt[base + 1];
    if (base + 2 < M) v2 = cnt[base + 2];
    if (base + 3 < M) v3 = cnt[base + 3];
    const int tsum = v0 + v1 + v2 + v3;
    const int lane = t & 31, wid = t >> 5;
    int x = tsum;
#pragma unroll
    for (int o = 1; o < 32; o <<= 1) {
        int y = __shfl_up_sync(~0u, x, o);
        if (lane >= o) x += y;
    }
    if (lane == 31) wsum[wid] = x;
    __syncthreads();
    if (wid == 0) {
        int w = (lane < 8) ? wsum[lane] : 0;
#pragma unroll
        for (int o = 1; o < 8; o <<= 1) {
            int y = __shfl_up_sync(~0u, w, o);
            if (lane >= o) w += y;
        }
        if (lane < 8) wsum[lane] = w;
    }
    __syncthreads();
    const int excl = x - tsum + (wid > 0 ? wsum[wid - 1] : 0);
    if (base + 0 < M) off[base + 0] = excl;
    if (base + 1 < M) off[base + 1] = excl + v0;
    if (base + 2 < M) off[base + 2] = excl + v0 + v1;
    if (base + 3 < M) off[base + 3] = excl + v0 + v1 + v2;
    if (t == 0) bsum[blockIdx.x] = wsum[7];
}
// Pass 2: one block scans the (<=1024) block totals in shared memory
__global__ void scan2_k(int* __restrict__ bsum, int nb) {
    __shared__ int sh[1024];
    const int t = threadIdx.x;
    sh[t] = (t < nb) ? bsum[t] : 0;
    __syncthreads();
    for (int o = 1; o < 1024; o <<= 1) {
        int v = (t >= o) ? sh[t - o] : 0;
        __syncthreads();
        sh[t] += v;
        __syncthreads();
    }
    if (t < nb) bsum[t] = sh[t] - ((t < nb) ? ((t == 0) ? sh[0] : sh[t] - sh[t - 1]) : 0);
    // rewrite exclusively: bsum[t] = inclusive - own = sh[t-1] (or 0)
    if (t < nb) bsum[t] = (t == 0) ? 0 : sh[t - 1];
}
// Pass 3: add block offsets; also initialize cursors
__global__ void scan3_k(int* __restrict__ off, int* __restrict__ cur,
                        const int* __restrict__ bsum, int M) {
    int i = blockIdx.x * blockDim.x + threadIdx.x;
    if (i < M) {
        int v = off[i] + bsum[i >> 10];
        off[i] = v;
        cur[i] = v;
    }
}
__global__ void scatter_k(const int* __restrict__ ei, const int* __restrict__ et,
                          int* __restrict__ cur, int* __restrict__ srcv, int E) {
    int e = blockIdx.x * blockDim.x + threadIdx.x;
    if (e < E) {
        const int sh = g_shift;
        int s = ei[e << sh];
        int d = ei[(E << sh) + (e << sh)];
        int r = et[e << sh];
        if ((unsigned)d < NN && (unsigned)r < RR && (unsigned)s < NN) {
            int pos = atomicAdd(&cur[r * NN + d], 1);
            srcv[pos] = s;
        }
    }
}

// ---------------------------------------------------------------------------
// Split / fuse kernels
// ---------------------------------------------------------------------------
__global__ void split_k(const float* __restrict__ A, __nv_bfloat16* __restrict__ H,
                        __nv_bfloat16* __restrict__ L, size_t n4) {
    size_t i = (size_t)blockIdx.x * blockDim.x + threadIdx.x;
    if (i < n4) {
        float4 v = ((const float4*)A)[i];
        __nv_bfloat162 h0 = __floats2bfloat162_rn(v.x, v.y);
        __nv_bfloat162 h1 = __floats2bfloat162_rn(v.z, v.w);
        __nv_bfloat162 l0 = __floats2bfloat162_rn(v.x - __bfloat162float(h0.x),
                                                  v.y - __bfloat162float(h0.y));
        __nv_bfloat162 l1 = __floats2bfloat162_rn(v.z - __bfloat162float(h1.x),
                                                  v.w - __bfloat162float(h1.y));
        ((__nv_bfloat162*)H)[2 * i]     = h0;
        ((__nv_bfloat162*)H)[2 * i + 1] = h1;
        ((__nv_bfloat162*)L)[2 * i]     = l0;
        ((__nv_bfloat162*)L)[2 * i + 1] = l1;
    }
}
// relu + split fused (h itself is not needed after this)
__global__ void relu_split_k(const float* __restrict__ A, __nv_bfloat16* __restrict__ H,
                             __nv_bfloat16* __restrict__ L, size_t n4) {
    size_t i = (size_t)blockIdx.x * blockDim.x + threadIdx.x;
    if (i < n4) {
        float4 v = ((const float4*)A)[i];
        v.x = fmaxf(v.x, 0.f); v.y = fmaxf(v.y, 0.f);
        v.z = fmaxf(v.z, 0.f); v.w = fmaxf(v.w, 0.f);
        __nv_bfloat162 h0 = __floats2bfloat162_rn(v.x, v.y);
        __nv_bfloat162 h1 = __floats2bfloat162_rn(v.z, v.w);
        __nv_bfloat162 l0 = __floats2bfloat162_rn(v.x - __bfloat162float(h0.x),
                                                  v.y - __bfloat162float(h0.y));
        __nv_bfloat162 l1 = __floats2bfloat162_rn(v.z - __bfloat162float(h1.x),
                                                  v.w - __bfloat162float(h1.y));
        ((__nv_bfloat162*)H)[2 * i]     = h0;
        ((__nv_bfloat162*)H)[2 * i + 1] = h1;
        ((__nv_bfloat162*)L)[2 * i]     = l0;
        ((__nv_bfloat162*)L)[2 * i + 1] = l1;
    }
}
__global__ void splitw_k(const float* __restrict__ W, __nv_bfloat16* __restrict__ H,
                         __nv_bfloat16* __restrict__ L, int nmat) {
    int idx = blockIdx.x * blockDim.x + threadIdx.x;
    int total = nmat * DD * DD;
    if (idx < total) {
        int m = idx >> 14;
        int rem = idx & 16383;
        int n = rem >> 7;
        int k = rem & 127;
        float v = W[(m << 14) + (k << 7) + n];
        __nv_bfloat16 h = __float2bfloat16(v);
        __nv_bfloat16 l = __float2bfloat16(v - __bfloat162float(h));
        H[idx] = h;
        L[idx] = l;
    }
}

// ---------------------------------------------------------------------------
// Tensor-core GEMM (mma.sync, portable PTX) — validated in R5.
// ---------------------------------------------------------------------------
#define SSTR 136
#define TILE_BYTES (128 * SSTR * 2)
#define GSMEM (4 * TILE_BYTES)

static __device__ __forceinline__ uint32_t smem_u32(const void* p) {
    uint32_t a;
    asm("{ .reg .u64 t; cvta.to.shared.u64 t, %1; cvt.u32.u64 %0, t; }"
        : "=r"(a) : "l"(p));
    return a;
}
#define LDSM_X4(r0, r1, r2, r3, addr) \
    asm volatile("ldmatrix.sync.aligned.m8n8.x4.shared.b16 {%0,%1,%2,%3}, [%4];" \
                 : "=r"(r0), "=r"(r1), "=r"(r2), "=r"(r3) : "r"(addr))
#define MMA16816(d, a, b0, b1) \
    asm volatile("mma.sync.aligned.m16n8k16.row.col.f32.bf16.bf16.f32 " \
                 "{%0,%1,%2,%3}, {%4,%5,%6,%7}, {%8,%9}, {%0,%1,%2,%3};" \
                 : "+f"((d)[0]), "+f"((d)[1]), "+f"((d)[2]), "+f"((d)[3]) \
                 : "r"((a)[0]), "r"((a)[1]), "r"((a)[2]), "r"((a)[3]), \
                   "r"(b0), "r"(b1))

__global__ void __launch_bounds__(256, 1)
gemm_tc_k(const __nv_bfloat16* __restrict__ Ah, const __nv_bfloat16* __restrict__ Al,
          const __nv_bfloat16* __restrict__ Bh, const __nv_bfloat16* __restrict__ Bl,
          const float* __restrict__ bias, float* __restrict__ C, int M) {
    extern __shared__ char smc[];
    __nv_bfloat16* sAh = (__nv_bfloat16*)smc;
    __nv_bfloat16* sAl = (__nv_bfloat16*)(smc + TILE_BYTES);
    __nv_bfloat16* sBh = (__nv_bfloat16*)(smc + 2 * TILE_BYTES);
    __nv_bfloat16* sBl = (__nv_bfloat16*)(smc + 3 * TILE_BYTES);

    const int t   = threadIdx.x;
    const int wid = t >> 5, lid = t & 31;
    const int m0  = blockIdx.x * 128;

#pragma unroll
    for (int it = 0; it < 8; it++) {
        const int idx = it * 256 + t;
        const int row = idx >> 4;
        const int c16 = (idx & 15) * 8;
        const int soff = row * SSTR + c16;
        *(uint4*)(sBh + soff) = *(const uint4*)(Bh + row * DD + c16);
        *(uint4*)(sBl + soff) = *(const uint4*)(Bl + row * DD + c16);
        uint4 vh = make_uint4(0, 0, 0, 0), vl = make_uint4(0, 0, 0, 0);
        const int gr = m0 + row;
        if (gr < M) {
            vh = *(const uint4*)(Ah + (size_t)gr * DD + c16);
            vl = *(const uint4*)(Al + (size_t)gr * DD + c16);
        }
        *(uint4*)(sAh + soff) = vh;
        *(uint4*)(sAl + soff) = vl;
    }
    __syncthreads();

    const int warpM = (wid & 3) * 32;
    const int warpN = (wid >> 2) * 64;

    float acc[2][8][4];
#pragma unroll
    for (int i = 0; i < 2; i++)
#pragma unroll
        for (int j = 0; j < 8; j++)
#pragma unroll
            for (int c = 0; c < 4; c++) acc[i][j][c] = 0.0f;

    const int aRow = warpM + (lid & 15);
    const int aK   = (lid >> 4) << 3;
    const int bN   = warpN + (lid & 7) + ((lid >> 4) << 3);
    const int bK   = ((lid >> 3) & 1) << 3;

    const uint32_t uAh = smem_u32(sAh), uAl = smem_u32(sAl);
    const uint32_t uBh = smem_u32(sBh), uBl = smem_u32(sBl);

#pragma unroll
    for (int pass = 0; pass < 3; pass++) {
        const uint32_t ua = (pass == 1) ? uAl : uAh;
        const uint32_t ub = (pass == 2) ? uBl : uBh;
#pragma unroll
        for (int k0 = 0; k0 < 128; k0 += 16) {
            uint32_t a[2][4];
#pragma unroll
            for (int mi = 0; mi < 2; mi++) {
                const uint32_t addr = ua + (uint32_t)(((aRow + mi * 16) * SSTR
                                                       + (aK + k0)) * 2);
                LDSM_X4(a[mi][0], a[mi][1], a[mi][2], a[mi][3], addr);
            }
            uint32_t b[4][4];
#pragma unroll
            for (int bq = 0; bq < 4; bq++) {
                const uint32_t addr = ub + (uint32_t)(((bN + bq * 16) * SSTR
                                                       + (bK + k0)) * 2);
                LDSM_X4(b[bq][0], b[bq][1], b[bq][2], b[bq][3], addr);
            }
#pragma unroll
            for (int mi = 0; mi < 2; mi++)
#pragma unroll
                for (int nj = 0; nj < 8; nj++) {
                    const int bq = nj >> 1, hi = (nj & 1) << 1;
                    MMA16816(acc[mi][nj], a[mi], b[bq][hi], b[bq][hi + 1]);
                }
        }
    }

    const int g  = lid >> 2;
    const int tg = lid & 3;
#pragma unroll
    for (int mi = 0; mi < 2; mi++) {
#pragma unroll
        for (int nj = 0; nj < 8; nj++) {
            const int col = warpN + nj * 8 + tg * 2;
            float bx = 0.f, by = 0.f;
            if (bias) { bx = bias[col]; by = bias[col + 1]; }
            const int r0 = m0 + warpM + mi * 16 + g;
            const int r1 = r0 + 8;
            if (r0 < M) {
                float2 v = make_float2(acc[mi][nj][0] + bx, acc[mi][nj][1] + by);
                *(float2*)(C + (size_t)r0 * DD + col) = v;
            }
            if (r1 < M) {
                float2 v = make_float2(acc[mi][nj][2] + bx, acc[mi][nj][3] + by);
                *(float2*)(C + (size_t)r1 * DD + col) = v;
            }
        }
    }
}

// ---------------------------------------------------------------------------
// Segmented aggregation for relation r: one warp per dst bin; sum the bin's
// gathered xr rows in registers; single plain float4 RMW of out[dst].
// No global atomics.
// ---------------------------------------------------------------------------
__global__ void agg_k(const int* __restrict__ off, const int* __restrict__ srcv,
                      const float* __restrict__ msg, float* __restrict__ out,
                      int r, int E) {
    const int w = (blockIdx.x * blockDim.x + threadIdx.x) >> 5;  // dst id
    if (w >= NN) return;
    const int lane = threadIdx.x & 31;
    const int k  = r * NN + w;
    const int lo = off[k];
    const int hi = (k == MBINS - 1) ? E : off[k + 1];
    if (lo == hi) return;

    float4 acc = make_float4(0.f, 0.f, 0.f, 0.f);
    for (int i = lo; i < hi; i++) {
        const int s = srcv[i];  // broadcast load (all lanes same address)
        const float4 v = *(const float4*)(msg + (size_t)s * DD + lane * 4);
        acc.x += v.x; acc.y += v.y; acc.z += v.z; acc.w += v.w;
    }
    const float inv = 1.0f / (float)(hi - lo);
    float* p = out + (size_t)w * DD + lane * 4;
    float4 o = *(const float4*)p;
    o.x += acc.x * inv; o.y += acc.y * inv; o.z += acc.z * inv; o.w += acc.w * inv;
    *(float4*)p = o;
}

// ---------------------------------------------------------------------------
// Launch
// ---------------------------------------------------------------------------
extern "C" void kernel_launch(void* const* d_in, const int* in_sizes, int n_in,
                              void* d_out, int out_size) {
    const float* x     = (const float*)d_in[0];
    const int*   ei    = (const int*)d_in[1];
    const int*   et    = (const int*)d_in[2];
    const float* W1    = (const float*)d_in[3];
    const float* root1 = (const float*)d_in[4];
    const float* b1    = (const float*)d_in[5];
    const float* W2    = (const float*)d_in[6];
    const float* root2 = (const float*)d_in[7];
    const float* b2    = (const float*)d_in[8];
    float* out = (float*)d_out;

    const int E = in_sizes[1] / 2;
    const int N = in_sizes[0] / DD;

    float *xr, *h;
    __nv_bfloat16 *ah, *al, *wh, *wl;
    int *cnt, *off, *cur, *bsum, *srcv;
    cudaGetSymbolAddress((void**)&xr,   g_xr);
    cudaGetSymbolAddress((void**)&h,    g_h);
    cudaGetSymbolAddress((void**)&ah,   g_ah);
    cudaGetSymbolAddress((void**)&al,   g_al);
    cudaGetSymbolAddress((void**)&wh,   g_wh);
    cudaGetSymbolAddress((void**)&wl,   g_wl);
    cudaGetSymbolAddress((void**)&cnt,  g_cnt);
    cudaGetSymbolAddress((void**)&off,  g_off);
    cudaGetSymbolAddress((void**)&cur,  g_cur);
    cudaGetSymbolAddress((void**)&bsum, g_bsum);
    cudaGetSymbolAddress((void**)&srcv, g_src);

    cudaFuncSetAttribute(gemm_tc_k, cudaFuncAttributeMaxDynamicSharedMemorySize, GSMEM);

    const int gemm_grid = (N + 127) / 128;
    const int agg_grid  = (NN * 32 + 255) / 256;   // one warp per dst
    const int nb = (MBINS + 1023) / 1024;
    const size_t n4 = (size_t)N * DD / 4;

    // ---- Edge preprocessing: counting sort by (rel, dst) ----
    detect_k<<<1, 256>>>(et, E);
    zero_cnt_k<<<(MBINS + 255) / 256, 256>>>(cnt, MBINS);
    count_k<<<(E + 255) / 256, 256>>>(ei, et, cnt, E);
    scan1_k<<<nb, 256>>>(cnt, off, bsum, MBINS);
    scan2_k<<<1, 1024>>>(bsum, nb);
    scan3_k<<<(MBINS + 255) / 256, 256>>>(off, cur, bsum, MBINS);
    scatter_k<<<(E + 255) / 256, 256>>>(ei, et, cur, srcv, E);

    // ---- Layer 1 ----
    split_k<<<(int)((n4 + 255) / 256), 256>>>(x, ah, al, n4);
    splitw_k<<<(DD * DD + 255) / 256, 256>>>(root1, wh, wl, 1);
    splitw_k<<<(RR * DD * DD + 255) / 256, 256>>>(W1, wh + DD * DD, wl + DD * DD, RR);

    gemm_tc_k<<<gemm_grid, 256, GSMEM>>>(ah, al, wh, wl, b1, h, N);
    for (int r = 0; r < RR; r++) {
        gemm_tc_k<<<gemm_grid, 256, GSMEM>>>(ah, al, wh + (size_t)(r + 1) * DD * DD,
                                             wl + (size_t)(r + 1) * DD * DD, nullptr, xr, N);
        agg_k<<<agg_grid, 256>>>(off, srcv, xr, h, r, E);
    }
    relu_split_k<<<(int)((n4 + 255) / 256), 256>>>(h, ah, al, n4);

    // ---- Layer 2 ----
    splitw_k<<<(DD * DD + 255) / 256, 256>>>(root2, wh, wl, 1);
    splitw_k<<<(RR * DD * DD + 255) / 256, 256>>>(W2, wh + DD * DD, wl + DD * DD, RR);

    gemm_tc_k<<<gemm_grid, 256, GSMEM>>>(ah, al, wh, wl, b2, out, N);
    for (int r = 0; r < RR; r++) {
        gemm_tc_k<<<gemm_grid, 256, GSMEM>>>(ah, al, wh + (size_t)(r + 1) * DD * DD,
                                             wl + (size_t)(r + 1) * DD * DD, nullptr, xr, N);
        agg_k<<<agg_grid, 256>>>(off, srcv, xr, out, r, E);
    }
}

// round 7
// speedup vs baseline: 1.4387x; 1.4387x over previous
#include <cuda_runtime.h>
#include <cuda_bf16.h>
#include <cstdint>

#define NN 100000
#define EE 1600000
#define RR 8
#define DD 128
#define RS 1152            // row stride of the big output: 9 * 128

// ---------------------------------------------------------------------------
// Scratch (device globals; no allocation allowed anywhere).
// ---------------------------------------------------------------------------
__device__ __align__(16) float g_big[(size_t)NN * RS];   // [N][root | 8 relation blocks]
__device__ __align__(16) float g_h [(size_t)NN * DD];    // hidden activations
__device__ __align__(16) __nv_bfloat16 g_wh[9 * DD * DD];  // [mat][n][k] weights hi
__device__ __align__(16) __nv_bfloat16 g_wl[9 * DD * DD];  // [mat][n][k] weights residual
__device__ int g_cnt8[NN * RR];   // per-(dst,rel) counts (dst-major) -> norms
__device__ int g_cntd[NN];        // per-dst counts
__device__ int g_offd[NN];        // exclusive dst offsets
__device__ int g_curd[NN];        // scatter cursors
__device__ int g_bsum[1024];      // scan block partials
__device__ int g_pack[EE];        // (rel<<17)|src, sorted by dst
__device__ int g_shift;           // 1 if edge arrays are int64, 0 if int32

// ---------------------------------------------------------------------------
// dtype autodetect (int64 edges => all odd 32-bit words zero)
// ---------------------------------------------------------------------------
__global__ void detect_k(const int* __restrict__ et, int E) {
    __shared__ int any;
    if (threadIdx.x == 0) any = 0;
    __syncthreads();
    int n = min(E, 4096);
    int local = 0;
    for (int i = threadIdx.x; i < n; i += blockDim.x) local |= et[2 * i + 1];
    if (local) atomicOr(&any, 1);
    __syncthreads();
    if (threadIdx.x == 0) g_shift = any ? 0 : 1;
}

// ---------------------------------------------------------------------------
// Counting sort by dst (rel packed into value)
// ---------------------------------------------------------------------------
__global__ void zero_cnt_k(int* __restrict__ c8, int* __restrict__ cd) {
    int i = blockIdx.x * blockDim.x + threadIdx.x;
    if (i < NN * RR) c8[i] = 0;
    if (i < NN) cd[i] = 0;
}
__global__ void count_k(const int* __restrict__ ei, const int* __restrict__ et,
                        int* __restrict__ c8, int* __restrict__ cd, int E) {
    int e = blockIdx.x * blockDim.x + threadIdx.x;
    if (e < E) {
        const int sh = g_shift;
        int d = ei[(E << sh) + (e << sh)];
        int r = et[e << sh];
        if ((unsigned)d < NN && (unsigned)r < RR) {
            atomicAdd(&c8[d * RR + r], 1);
            atomicAdd(&cd[d], 1);
        }
    }
}
__global__ void scan1_k(const int* __restrict__ cnt, int* __restrict__ off,
                        int* __restrict__ bsum, int M) {
    __shared__ int wsum[8];
    const int t = threadIdx.x;
    const int base = blockIdx.x * 1024 + t * 4;
    int v0 = 0, v1 = 0, v2 = 0, v3 = 0;
    if (base + 0 < M) v0 = cnt[base + 0];
    if (base + 1 < M) v1 = cnt[base + 1];
    if (base + 2 < M) v2 = cnt[base + 2];
    if (base + 3 < M) v3 = cnt[base + 3];
    const int tsum = v0 + v1 + v2 + v3;
    const int lane = t & 31, wid = t >> 5;
    int x = tsum;
#pragma unroll
    for (int o = 1; o < 32; o <<= 1) {
        int y = __shfl_up_sync(~0u, x, o);
        if (lane >= o) x += y;
    }
    if (lane == 31) wsum[wid] = x;
    __syncthreads();
    if (wid == 0) {
        int w = (lane < 8) ? wsum[lane] : 0;
#pragma unroll
        for (int o = 1; o < 8; o <<= 1) {
            int y = __shfl_up_sync(~0u, w, o);
            if (lane >= o) w += y;
        }
        if (lane < 8) wsum[lane] = w;
    }
    __syncthreads();
    const int excl = x - tsum + (wid > 0 ? wsum[wid - 1] : 0);
    if (base + 0 < M) off[base + 0] = excl;
    if (base + 1 < M) off[base + 1] = excl + v0;
    if (base + 2 < M) off[base + 2] = excl + v0 + v1;
    if (base + 3 < M) off[base + 3] = excl + v0 + v1 + v2;
    if (t == 0) bsum[blockIdx.x] = wsum[7];
}
__global__ void scan2_k(int* __restrict__ bsum, int nb) {
    __shared__ int sh[1024];
    const int t = threadIdx.x;
    sh[t] = (t < nb) ? bsum[t] : 0;
    __syncthreads();
    for (int o = 1; o < 1024; o <<= 1) {
        int v = (t >= o) ? sh[t - o] : 0;
        __syncthreads();
        sh[t] += v;
        __syncthreads();
    }
    if (t < nb) bsum[t] = (t == 0) ? 0 : sh[t - 1];
}
__global__ void scan3_k(int* __restrict__ off, int* __restrict__ cur,
                        const int* __restrict__ bsum, int M) {
    int i = blockIdx.x * blockDim.x + threadIdx.x;
    if (i < M) {
        int v = off[i] + bsum[i >> 10];
        off[i] = v;
        cur[i] = v;
    }
}
__global__ void scatter_k(const int* __restrict__ ei, const int* __restrict__ et,
                          int* __restrict__ cur, int* __restrict__ pack, int E) {
    int e = blockIdx.x * blockDim.x + threadIdx.x;
    if (e < E) {
        const int sh = g_shift;
        int s = ei[e << sh];
        int d = ei[(E << sh) + (e << sh)];
        int r = et[e << sh];
        if ((unsigned)d < NN && (unsigned)r < RR && (unsigned)s < NN) {
            int pos = atomicAdd(&cur[d], 1);
            pack[pos] = (r << 17) | s;
        }
    }
}

// ---------------------------------------------------------------------------
// Weight transpose + split: out[mat][n][k], mat 0 = root, 1..8 = W[r]
// ---------------------------------------------------------------------------
__global__ void splitw9_k(const float* __restrict__ root, const float* __restrict__ W,
                          __nv_bfloat16* __restrict__ H, __nv_bfloat16* __restrict__ L) {
    int idx = blockIdx.x * blockDim.x + threadIdx.x;
    if (idx < 9 * DD * DD) {
        int mat = idx >> 14;
        int rem = idx & 16383;
        int n = rem >> 7;
        int k = rem & 127;
        float v = (mat == 0) ? root[(k << 7) + n] : W[((mat - 1) << 14) + (k << 7) + n];
        __nv_bfloat16 h = __float2bfloat16(v);
        __nv_bfloat16 l = __float2bfloat16(v - __bfloat162float(h));
        H[idx] = h;
        L[idx] = l;
    }
}

// ---------------------------------------------------------------------------
// Batched tensor-core GEMM: Cbig[M,1152] = A[M,128] @ {9 weight mats} (+bias on
// mat 0). A read as fp32 and split to bf16h/l in registers, resident in smem
// for all 9 mats. B double-buffered via cp.async. mma.sync bf16, 3 passes.
// ---------------------------------------------------------------------------
#define SSTR 136
#define TILE_BYTES (128 * SSTR * 2)     // 34816
#define GSMEM (6 * TILE_BYTES)          // Ah, Al, B double-buffer (h,l) x2

static __device__ __forceinline__ uint32_t smem_u32(const void* p) {
    uint32_t a;
    asm("{ .reg .u64 t; cvta.to.shared.u64 t, %1; cvt.u32.u64 %0, t; }"
        : "=r"(a) : "l"(p));
    return a;
}
#define LDSM_X4(r0, r1, r2, r3, addr) \
    asm volatile("ldmatrix.sync.aligned.m8n8.x4.shared.b16 {%0,%1,%2,%3}, [%4];" \
                 : "=r"(r0), "=r"(r1), "=r"(r2), "=r"(r3) : "r"(addr))
#define MMA16816(d, a, b0, b1) \
    asm volatile("mma.sync.aligned.m16n8k16.row.col.f32.bf16.bf16.f32 " \
                 "{%0,%1,%2,%3}, {%4,%5,%6,%7}, {%8,%9}, {%0,%1,%2,%3};" \
                 : "+f"((d)[0]), "+f"((d)[1]), "+f"((d)[2]), "+f"((d)[3]) \
                 : "r"((a)[0]), "r"((a)[1]), "r"((a)[2]), "r"((a)[3]), \
                   "r"(b0), "r"(b1))
#define CP_ASYNC16(saddr, gptr) \
    asm volatile("cp.async.cg.shared.global [%0], [%1], 16;" \
                 :: "r"(saddr), "l"(gptr))

static __device__ __forceinline__ void prefetchB(
    const __nv_bfloat16* __restrict__ Wh, const __nv_bfloat16* __restrict__ Wl,
    uint32_t uBh, uint32_t uBl, int mat, int t) {
    const __nv_bfloat16* bh = Wh + (size_t)mat * DD * DD;
    const __nv_bfloat16* bl = Wl + (size_t)mat * DD * DD;
#pragma unroll
    for (int it = 0; it < 8; it++) {
        const int idx = it * 256 + t;
        const int row = idx >> 4;
        const int c16 = (idx & 15) * 8;
        const uint32_t soff = (uint32_t)(row * SSTR + c16) * 2;
        CP_ASYNC16(uBh + soff, bh + row * DD + c16);
        CP_ASYNC16(uBl + soff, bl + row * DD + c16);
    }
}

__global__ void __launch_bounds__(256, 1)
gemm9_k(const float* __restrict__ A, const __nv_bfloat16* __restrict__ Wh,
        const __nv_bfloat16* __restrict__ Wl, const float* __restrict__ bias,
        float* __restrict__ Cbig, int M) {
    extern __shared__ char smc[];
    __nv_bfloat16* sAh = (__nv_bfloat16*)smc;
    __nv_bfloat16* sAl = (__nv_bfloat16*)(smc + TILE_BYTES);
    const uint32_t uAh = smem_u32(sAh), uAl = smem_u32(sAl);
    const uint32_t uB0h = uAh + 2 * TILE_BYTES, uB0l = uAh + 3 * TILE_BYTES;
    const uint32_t uB1h = uAh + 4 * TILE_BYTES, uB1l = uAh + 5 * TILE_BYTES;

    const int t   = threadIdx.x;
    const int wid = t >> 5, lid = t & 31;
    const int m0  = blockIdx.x * 128;

    // Kick off B[0] prefetch first so it overlaps the A fp32 load+split.
    prefetchB(Wh, Wl, uB0h, uB0l, 0, t);
    asm volatile("cp.async.commit_group;");

    // A tile: read fp32, split to bf16 hi/residual in registers, store smem.
#pragma unroll
    for (int it = 0; it < 16; it++) {
        const int idx = it * 256 + t;
        const int row = idx >> 5;
        const int c4  = (idx & 31) * 4;
        float4 v = make_float4(0.f, 0.f, 0.f, 0.f);
        const int gr = m0 + row;
        if (gr < M) v = *(const float4*)(A + (size_t)gr * DD + c4);
        __nv_bfloat162 h01 = __floats2bfloat162_rn(v.x, v.y);
        __nv_bfloat162 h23 = __floats2bfloat162_rn(v.z, v.w);
        __nv_bfloat162 l01 = __floats2bfloat162_rn(v.x - __bfloat162float(h01.x),
                                                   v.y - __bfloat162float(h01.y));
        __nv_bfloat162 l23 = __floats2bfloat162_rn(v.z - __bfloat162float(h23.x),
                                                   v.w - __bfloat162float(h23.y));
        const int soff = row * SSTR + c4;
        *(__nv_bfloat162*)(sAh + soff)     = h01;
        *(__nv_bfloat162*)(sAh + soff + 2) = h23;
        *(__nv_bfloat162*)(sAl + soff)     = l01;
        *(__nv_bfloat162*)(sAl + soff + 2) = l23;
    }

    const int warpM = (wid & 3) * 32;
    const int warpN = (wid >> 2) * 64;
    const int aRow = warpM + (lid & 15);
    const int aK   = (lid >> 4) << 3;
    const int bN   = warpN + (lid & 7) + ((lid >> 4) << 3);
    const int bK   = ((lid >> 3) & 1) << 3;
    const int g    = lid >> 2;
    const int tg   = lid & 3;

    for (int mat = 0; mat < 9; mat++) {
        if (mat < 8) {
            prefetchB(Wh, Wl, (mat & 1) ? uB0h : uB1h, (mat & 1) ? uB0l : uB1l,
                      mat + 1, t);
            asm volatile("cp.async.commit_group;");
            asm volatile("cp.async.wait_group 1;");
        } else {
            asm volatile("cp.async.wait_group 0;");
        }
        __syncthreads();

        const uint32_t ubh = (mat & 1) ? uB1h : uB0h;
        const uint32_t ubl = (mat & 1) ? uB1l : uB0l;

        float acc[2][8][4];
#pragma unroll
        for (int i = 0; i < 2; i++)
#pragma unroll
            for (int j = 0; j < 8; j++)
#pragma unroll
                for (int c = 0; c < 4; c++) acc[i][j][c] = 0.0f;

#pragma unroll
        for (int pass = 0; pass < 3; pass++) {
            const uint32_t ua = (pass == 1) ? uAl : uAh;
            const uint32_t ub = (pass == 2) ? ubl : ubh;
#pragma unroll
            for (int k0 = 0; k0 < 128; k0 += 16) {
                uint32_t a[2][4];
#pragma unroll
                for (int mi = 0; mi < 2; mi++) {
                    const uint32_t addr = ua + (uint32_t)(((aRow + mi * 16) * SSTR
                                                           + (aK + k0)) * 2);
                    LDSM_X4(a[mi][0], a[mi][1], a[mi][2], a[mi][3], addr);
                }
                uint32_t b[4][4];
#pragma unroll
                for (int bq = 0; bq < 4; bq++) {
                    const uint32_t addr = ub + (uint32_t)(((bN + bq * 16) * SSTR
                                                           + (bK + k0)) * 2);
                    LDSM_X4(b[bq][0], b[bq][1], b[bq][2], b[bq][3], addr);
                }
#pragma unroll
                for (int mi = 0; mi < 2; mi++)
#pragma unroll
                    for (int nj = 0; nj < 8; nj++) {
                        const int bq = nj >> 1, hi = (nj & 1) << 1;
                        MMA16816(acc[mi][nj], a[mi], b[bq][hi], b[bq][hi + 1]);
                    }
            }
        }

        // Epilogue for this matrix: col block mat*128 of Cbig (row stride RS)
        const int cb = mat * 128;
#pragma unroll
        for (int mi = 0; mi < 2; mi++) {
#pragma unroll
            for (int nj = 0; nj < 8; nj++) {
                const int col = warpN + nj * 8 + tg * 2;
                float bx = 0.f, by = 0.f;
                if (mat == 0 && bias) { bx = bias[col]; by = bias[col + 1]; }
                const int r0 = m0 + warpM + mi * 16 + g;
                const int r1 = r0 + 8;
                if (r0 < M) {
                    float2 v = make_float2(acc[mi][nj][0] + bx, acc[mi][nj][1] + by);
                    *(float2*)(Cbig + (size_t)r0 * RS + cb + col) = v;
                }
                if (r1 < M) {
                    float2 v = make_float2(acc[mi][nj][2] + bx, acc[mi][nj][3] + by);
                    *(float2*)(Cbig + (size_t)r1 * RS + cb + col) = v;
                }
            }
        }
        __syncthreads();  // all warps done reading this B buffer before reuse
    }
}

// ---------------------------------------------------------------------------
// Single-pass aggregation: one warp per dst.
// out[dst] = maybe_relu( big[dst][0:128] + sum_e big[src_e][128*(1+rel_e)..]
//                                          * inv_cnt[dst][rel_e] )
// No atomics; each output row written exactly once.
// ---------------------------------------------------------------------------
__global__ void agg_k(const int* __restrict__ offd, const int* __restrict__ pack,
                      const int* __restrict__ cnt8, const float* __restrict__ big,
                      float* __restrict__ out, int E, int do_relu) {
    const int d = (blockIdx.x * blockDim.x + threadIdx.x) >> 5;
    if (d >= NN) return;
    const int lane = threadIdx.x & 31;
    const int lo = offd[d];
    const int hi = (d == NN - 1) ? E : offd[d + 1];

    // lane r<8 holds 1/cnt for relation r
    float inv = 0.f;
    if (lane < RR) {
        int c = cnt8[d * RR + lane];
        inv = (c > 0) ? (1.0f / (float)c) : 0.f;
    }

    const int c4 = lane * 4;
    float4 acc;
    {   // root part (+bias already folded in by GEMM epilogue)
        acc = *(const float4*)(big + (size_t)d * RS + c4);
    }

    int i = lo;
    for (; i + 4 <= hi; i += 4) {
        const int p0 = pack[i], p1 = pack[i + 1], p2 = pack[i + 2], p3 = pack[i + 3];
        const float4 v0 = *(const float4*)(big + (size_t)(p0 & 0x1FFFF) * RS + 128 + ((p0 >> 17) << 7) + c4);
        const float4 v1 = *(const float4*)(big + (size_t)(p1 & 0x1FFFF) * RS + 128 + ((p1 >> 17) << 7) + c4);
        const float4 v2 = *(const float4*)(big + (size_t)(p2 & 0x1FFFF) * RS + 128 + ((p2 >> 17) << 7) + c4);
        const float4 v3 = *(const float4*)(big + (size_t)(p3 & 0x1FFFF) * RS + 128 + ((p3 >> 17) << 7) + c4);
        const float i0 = __shfl_sync(~0u, inv, p0 >> 17);
        const float i1 = __shfl_sync(~0u, inv, p1 >> 17);
        const float i2 = __shfl_sync(~0u, inv, p2 >> 17);
        const float i3 = __shfl_sync(~0u, inv, p3 >> 17);
        acc.x += v0.x * i0 + v1.x * i1 + v2.x * i2 + v3.x * i3;
        acc.y += v0.y * i0 + v1.y * i1 + v2.y * i2 + v3.y * i3;
        acc.z += v0.z * i0 + v1.z * i1 + v2.z * i2 + v3.z * i3;
        acc.w += v0.w * i0 + v1.w * i1 + v2.w * i2 + v3.w * i3;
    }
    for (; i < hi; i++) {
        const int p = pack[i];
        const float4 v = *(const float4*)(big + (size_t)(p & 0x1FFFF) * RS + 128 + ((p >> 17) << 7) + c4);
        const float iv = __shfl_sync(~0u, inv, p >> 17);
        acc.x += v.x * iv; acc.y += v.y * iv; acc.z += v.z * iv; acc.w += v.w * iv;
    }

    if (do_relu) {
        acc.x = fmaxf(acc.x, 0.f); acc.y = fmaxf(acc.y, 0.f);
        acc.z = fmaxf(acc.z, 0.f); acc.w = fmaxf(acc.w, 0.f);
    }
    *(float4*)(out + (size_t)d * DD + c4) = acc;
}

// ---------------------------------------------------------------------------
// Launch
// ---------------------------------------------------------------------------
extern "C" void kernel_launch(void* const* d_in, const int* in_sizes, int n_in,
                              void* d_out, int out_size) {
    const float* x     = (const float*)d_in[0];
    const int*   ei    = (const int*)d_in[1];
    const int*   et    = (const int*)d_in[2];
    const float* W1    = (const float*)d_in[3];
    const float* root1 = (const float*)d_in[4];
    const float* b1    = (const float*)d_in[5];
    const float* W2    = (const float*)d_in[6];
    const float* root2 = (const float*)d_in[7];
    const float* b2    = (const float*)d_in[8];
    float* out = (float*)d_out;

    const int E = in_sizes[1] / 2;
    const int N = in_sizes[0] / DD;

    float *big, *h;
    __nv_bfloat16 *wh, *wl;
    int *c8, *cd, *offd, *curd, *bsum, *pack;
    cudaGetSymbolAddress((void**)&big,  g_big);
    cudaGetSymbolAddress((void**)&h,    g_h);
    cudaGetSymbolAddress((void**)&wh,   g_wh);
    cudaGetSymbolAddress((void**)&wl,   g_wl);
    cudaGetSymbolAddress((void**)&c8,   g_cnt8);
    cudaGetSymbolAddress((void**)&cd,   g_cntd);
    cudaGetSymbolAddress((void**)&offd, g_offd);
    cudaGetSymbolAddress((void**)&curd, g_curd);
    cudaGetSymbolAddress((void**)&bsum, g_bsum);
    cudaGetSymbolAddress((void**)&pack, g_pack);

    cudaFuncSetAttribute(gemm9_k, cudaFuncAttributeMaxDynamicSharedMemorySize, GSMEM);

    const int gemm_grid = (N + 127) / 128;
    const int agg_grid  = (NN * 32 + 255) / 256;
    const int nb = (NN + 1023) / 1024;

    // Order chosen so gemm9_k is the 6th launch (ncu -s 5 -c 1 profiles it).
    detect_k<<<1, 256>>>(et, E);                                     // 0
    zero_cnt_k<<<(NN * RR + 255) / 256, 256>>>(c8, cd);              // 1
    count_k<<<(E + 255) / 256, 256>>>(ei, et, c8, cd, E);            // 2
    scan1_k<<<nb, 256>>>(cd, offd, bsum, NN);                        // 3
    splitw9_k<<<(9 * DD * DD + 255) / 256, 256>>>(root1, W1, wh, wl);// 4
    gemm9_k<<<gemm_grid, 256, GSMEM>>>(x, wh, wl, b1, big, N);       // 5 <- profiled
    scan2_k<<<1, 1024>>>(bsum, nb);                                  // 6
    scan3_k<<<(NN + 255) / 256, 256>>>(offd, curd, bsum, NN);        // 7
    scatter_k<<<(E + 255) / 256, 256>>>(ei, et, curd, pack, E);      // 8
    agg_k<<<agg_grid, 256>>>(offd, pack, c8, big, h, E, 1);          // 9

    splitw9_k<<<(9 * DD * DD + 255) / 256, 256>>>(root2, W2, wh, wl);// 10
    gemm9_k<<<gemm_grid, 256, GSMEM>>>(h, wh, wl, b2, big, N);       // 11
    agg_k<<<agg_grid, 256>>>(offd, pack, c8, big, out, E, 0);        // 12
}

// round 8
// speedup vs baseline: 1.8444x; 1.2820x over previous
#include <cuda_runtime.h>
#include <cuda_bf16.h>
#include <cuda_fp16.h>
#include <cstdint>

#define NN 100000
#define EE 1600000
#define RR 8
#define DD 128
#define MS 1024            // msg row stride: 8 relations * 128 (fp16)

// ---------------------------------------------------------------------------
// Scratch (device globals; no allocation allowed anywhere).
// ---------------------------------------------------------------------------
__device__ __align__(16) float  g_root[(size_t)NN * DD];  // root part (fp32, bias folded)
__device__ __align__(16) __half g_msg[(size_t)NN * MS];   // relation blocks (fp16)
__device__ __align__(16) float  g_h [(size_t)NN * DD];    // hidden activations
__device__ __align__(16) __nv_bfloat16 g_wh[9 * DD * DD]; // [mat][n][k] weights hi
__device__ __align__(16) __nv_bfloat16 g_wl[9 * DD * DD]; // [mat][n][k] weights residual
__device__ int g_cnt8[NN * RR];   // per-(dst,rel) counts
__device__ int g_cntd[NN];        // per-dst counts
__device__ int g_offd[NN];        // exclusive dst offsets
__device__ int g_curd[NN];        // scatter cursors
__device__ int g_bsum[1024];      // scan block partials
__device__ int g_pack[EE];        // (rel<<17)|src, sorted by dst
__device__ int g_shift;           // 1 if edge arrays are int64, 0 if int32

// ---------------------------------------------------------------------------
// dtype autodetect (int64 edges => all odd 32-bit words zero)
// ---------------------------------------------------------------------------
__global__ void detect_k(const int* __restrict__ et, int E) {
    __shared__ int any;
    if (threadIdx.x == 0) any = 0;
    __syncthreads();
    int n = min(E, 4096);
    int local = 0;
    for (int i = threadIdx.x; i < n; i += blockDim.x) local |= et[2 * i + 1];
    if (local) atomicOr(&any, 1);
    __syncthreads();
    if (threadIdx.x == 0) g_shift = any ? 0 : 1;
}

// ---------------------------------------------------------------------------
// Counting sort by dst (rel packed into value)
// ---------------------------------------------------------------------------
__global__ void zero_cnt_k(int* __restrict__ c8, int* __restrict__ cd) {
    int i = blockIdx.x * blockDim.x + threadIdx.x;
    if (i < NN * RR) c8[i] = 0;
    if (i < NN) cd[i] = 0;
}
__global__ void count_k(const int* __restrict__ ei, const int* __restrict__ et,
                        int* __restrict__ c8, int* __restrict__ cd, int E) {
    int e = blockIdx.x * blockDim.x + threadIdx.x;
    if (e < E) {
        const int sh = g_shift;
        int d = ei[(E << sh) + (e << sh)];
        int r = et[e << sh];
        if ((unsigned)d < NN && (unsigned)r < RR) {
            atomicAdd(&c8[d * RR + r], 1);
            atomicAdd(&cd[d], 1);
        }
    }
}
__global__ void scan1_k(const int* __restrict__ cnt, int* __restrict__ off,
                        int* __restrict__ bsum, int M) {
    __shared__ int wsum[8];
    const int t = threadIdx.x;
    const int base = blockIdx.x * 1024 + t * 4;
    int v0 = 0, v1 = 0, v2 = 0, v3 = 0;
    if (base + 0 < M) v0 = cnt[base + 0];
    if (base + 1 < M) v1 = cnt[base + 1];
    if (base + 2 < M) v2 = cnt[base + 2];
    if (base + 3 < M) v3 = cnt[base + 3];
    const int tsum = v0 + v1 + v2 + v3;
    const int lane = t & 31, wid = t >> 5;
    int x = tsum;
#pragma unroll
    for (int o = 1; o < 32; o <<= 1) {
        int y = __shfl_up_sync(~0u, x, o);
        if (lane >= o) x += y;
    }
    if (lane == 31) wsum[wid] = x;
    __syncthreads();
    if (wid == 0) {
        int w = (lane < 8) ? wsum[lane] : 0;
#pragma unroll
        for (int o = 1; o < 8; o <<= 1) {
            int y = __shfl_up_sync(~0u, w, o);
            if (lane >= o) w += y;
        }
        if (lane < 8) wsum[lane] = w;
    }
    __syncthreads();
    const int excl = x - tsum + (wid > 0 ? wsum[wid - 1] : 0);
    if (base + 0 < M) off[base + 0] = excl;
    if (base + 1 < M) off[base + 1] = excl + v0;
    if (base + 2 < M) off[base + 2] = excl + v0 + v1;
    if (base + 3 < M) off[base + 3] = excl + v0 + v1 + v2;
    if (t == 0) bsum[blockIdx.x] = wsum[7];
}
__global__ void scan2_k(int* __restrict__ bsum, int nb) {
    __shared__ int sh[1024];
    const int t = threadIdx.x;
    sh[t] = (t < nb) ? bsum[t] : 0;
    __syncthreads();
    for (int o = 1; o < 1024; o <<= 1) {
        int v = (t >= o) ? sh[t - o] : 0;
        __syncthreads();
        sh[t] += v;
        __syncthreads();
    }
    if (t < nb) bsum[t] = (t == 0) ? 0 : sh[t - 1];
}
__global__ void scan3_k(int* __restrict__ off, int* __restrict__ cur,
                        const int* __restrict__ bsum, int M) {
    int i = blockIdx.x * blockDim.x + threadIdx.x;
    if (i < M) {
        int v = off[i] + bsum[i >> 10];
        off[i] = v;
        cur[i] = v;
    }
}
__global__ void scatter_k(const int* __restrict__ ei, const int* __restrict__ et,
                          int* __restrict__ cur, int* __restrict__ pack, int E) {
    int e = blockIdx.x * blockDim.x + threadIdx.x;
    if (e < E) {
        const int sh = g_shift;
        int s = ei[e << sh];
        int d = ei[(E << sh) + (e << sh)];
        int r = et[e << sh];
        if ((unsigned)d < NN && (unsigned)r < RR && (unsigned)s < NN) {
            int pos = atomicAdd(&cur[d], 1);
            pack[pos] = (r << 17) | s;
        }
    }
}

// ---------------------------------------------------------------------------
// Weight transpose + split: out[mat][n][k], mat 0 = root, 1..8 = W[r]
// ---------------------------------------------------------------------------
__global__ void splitw9_k(const float* __restrict__ root, const float* __restrict__ W,
                          __nv_bfloat16* __restrict__ H, __nv_bfloat16* __restrict__ L) {
    int idx = blockIdx.x * blockDim.x + threadIdx.x;
    if (idx < 9 * DD * DD) {
        int mat = idx >> 14;
        int rem = idx & 16383;
        int n = rem >> 7;
        int k = rem & 127;
        float v = (mat == 0) ? root[(k << 7) + n] : W[((mat - 1) << 14) + (k << 7) + n];
        __nv_bfloat16 h = __float2bfloat16(v);
        __nv_bfloat16 l = __float2bfloat16(v - __bfloat162float(h));
        H[idx] = h;
        L[idx] = l;
    }
}

// ---------------------------------------------------------------------------
// Batched tensor-core GEMM: root (fp32) + 8 relation blocks (fp16) from
// A[M,128] @ {9 weight mats}. A split to bf16h/l in registers -> smem,
// B double-buffered via cp.async. Shared-fragment inner loop: per k-step load
// {ah, al, bh, bl} frags once and issue all 3 precision passes (48 MMAs).
// ---------------------------------------------------------------------------
#define SSTR 136
#define TILE_BYTES (128 * SSTR * 2)     // 34816
#define GSMEM (6 * TILE_BYTES)          // Ah, Al, B double-buffer (h,l) x2

static __device__ __forceinline__ uint32_t smem_u32(const void* p) {
    uint32_t a;
    asm("{ .reg .u64 t; cvta.to.shared.u64 t, %1; cvt.u32.u64 %0, t; }"
        : "=r"(a) : "l"(p));
    return a;
}
#define LDSM_X4(r0, r1, r2, r3, addr) \
    asm volatile("ldmatrix.sync.aligned.m8n8.x4.shared.b16 {%0,%1,%2,%3}, [%4];" \
                 : "=r"(r0), "=r"(r1), "=r"(r2), "=r"(r3) : "r"(addr))
#define MMA16816(d, a, b0, b1) \
    asm volatile("mma.sync.aligned.m16n8k16.row.col.f32.bf16.bf16.f32 " \
                 "{%0,%1,%2,%3}, {%4,%5,%6,%7}, {%8,%9}, {%0,%1,%2,%3};" \
                 : "+f"((d)[0]), "+f"((d)[1]), "+f"((d)[2]), "+f"((d)[3]) \
                 : "r"((a)[0]), "r"((a)[1]), "r"((a)[2]), "r"((a)[3]), \
                   "r"(b0), "r"(b1))
#define CP_ASYNC16(saddr, gptr) \
    asm volatile("cp.async.cg.shared.global [%0], [%1], 16;" \
                 :: "r"(saddr), "l"(gptr))

static __device__ __forceinline__ void prefetchB(
    const __nv_bfloat16* __restrict__ Wh, const __nv_bfloat16* __restrict__ Wl,
    uint32_t uBh, uint32_t uBl, int mat, int t) {
    const __nv_bfloat16* bh = Wh + (size_t)mat * DD * DD;
    const __nv_bfloat16* bl = Wl + (size_t)mat * DD * DD;
#pragma unroll
    for (int it = 0; it < 8; it++) {
        const int idx = it * 256 + t;
        const int row = idx >> 4;
        const int c16 = (idx & 15) * 8;
        const uint32_t soff = (uint32_t)(row * SSTR + c16) * 2;
        CP_ASYNC16(uBh + soff, bh + row * DD + c16);
        CP_ASYNC16(uBl + soff, bl + row * DD + c16);
    }
}

__global__ void __launch_bounds__(256, 1)
gemm9_k(const float* __restrict__ A, const __nv_bfloat16* __restrict__ Wh,
        const __nv_bfloat16* __restrict__ Wl, const float* __restrict__ bias,
        float* __restrict__ Croot, __half* __restrict__ Cmsg, int M) {
    extern __shared__ char smc[];
    __nv_bfloat16* sAh = (__nv_bfloat16*)smc;
    __nv_bfloat16* sAl = (__nv_bfloat16*)(smc + TILE_BYTES);
    const uint32_t uAh = smem_u32(sAh), uAl = smem_u32(sAl);
    const uint32_t uB0h = uAh + 2 * TILE_BYTES, uB0l = uAh + 3 * TILE_BYTES;
    const uint32_t uB1h = uAh + 4 * TILE_BYTES, uB1l = uAh + 5 * TILE_BYTES;

    const int t   = threadIdx.x;
    const int wid = t >> 5, lid = t & 31;
    const int m0  = blockIdx.x * 128;

    // Kick off B[0] prefetch first so it overlaps the A fp32 load+split.
    prefetchB(Wh, Wl, uB0h, uB0l, 0, t);
    asm volatile("cp.async.commit_group;");

    // A tile: read fp32, split to bf16 hi/residual in registers, store smem.
#pragma unroll
    for (int it = 0; it < 16; it++) {
        const int idx = it * 256 + t;
        const int row = idx >> 5;
        const int c4  = (idx & 31) * 4;
        float4 v = make_float4(0.f, 0.f, 0.f, 0.f);
        const int gr = m0 + row;
        if (gr < M) v = *(const float4*)(A + (size_t)gr * DD + c4);
        __nv_bfloat162 h01 = __floats2bfloat162_rn(v.x, v.y);
        __nv_bfloat162 h23 = __floats2bfloat162_rn(v.z, v.w);
        __nv_bfloat162 l01 = __floats2bfloat162_rn(v.x - __bfloat162float(h01.x),
                                                   v.y - __bfloat162float(h01.y));
        __nv_bfloat162 l23 = __floats2bfloat162_rn(v.z - __bfloat162float(h23.x),
                                                   v.w - __bfloat162float(h23.y));
        const int soff = row * SSTR + c4;
        *(__nv_bfloat162*)(sAh + soff)     = h01;
        *(__nv_bfloat162*)(sAh + soff + 2) = h23;
        *(__nv_bfloat162*)(sAl + soff)     = l01;
        *(__nv_bfloat162*)(sAl + soff + 2) = l23;
    }

    const int warpM = (wid & 3) * 32;
    const int warpN = (wid >> 2) * 64;
    const int aRow = warpM + (lid & 15);
    const int aK   = (lid >> 4) << 3;
    const int bN   = warpN + (lid & 7) + ((lid >> 4) << 3);
    const int bK   = ((lid >> 3) & 1) << 3;
    const int g    = lid >> 2;
    const int tg   = lid & 3;

    for (int mat = 0; mat < 9; mat++) {
        // Wait for this mat's B tile, publish it, then prefetch the next one.
        asm volatile("cp.async.wait_group 0;");
        __syncthreads();   // publishes B[mat]; proves B[mat-1] reads are done
        if (mat < 8) {
            prefetchB(Wh, Wl, (mat & 1) ? uB0h : uB1h, (mat & 1) ? uB0l : uB1l,
                      mat + 1, t);
            asm volatile("cp.async.commit_group;");
        }

        const uint32_t ubh = (mat & 1) ? uB1h : uB0h;
        const uint32_t ubl = (mat & 1) ? uB1l : uB0l;

        float acc[2][8][4];
#pragma unroll
        for (int i = 0; i < 2; i++)
#pragma unroll
            for (int j = 0; j < 8; j++)
#pragma unroll
                for (int c = 0; c < 4; c++) acc[i][j][c] = 0.0f;

#pragma unroll
        for (int k0 = 0; k0 < 128; k0 += 16) {
            uint32_t ah[2][4], al[2][4];
#pragma unroll
            for (int mi = 0; mi < 2; mi++) {
                const uint32_t ao = (uint32_t)(((aRow + mi * 16) * SSTR + (aK + k0)) * 2);
                LDSM_X4(ah[mi][0], ah[mi][1], ah[mi][2], ah[mi][3], uAh + ao);
                LDSM_X4(al[mi][0], al[mi][1], al[mi][2], al[mi][3], uAl + ao);
            }
            uint32_t bh[4][4], bl[4][4];
#pragma unroll
            for (int bq = 0; bq < 4; bq++) {
                const uint32_t bo = (uint32_t)(((bN + bq * 16) * SSTR + (bK + k0)) * 2);
                LDSM_X4(bh[bq][0], bh[bq][1], bh[bq][2], bh[bq][3], ubh + bo);
                LDSM_X4(bl[bq][0], bl[bq][1], bl[bq][2], bl[bq][3], ubl + bo);
            }
#pragma unroll
            for (int mi = 0; mi < 2; mi++)
#pragma unroll
                for (int nj = 0; nj < 8; nj++) {
                    const int bq = nj >> 1, hi = (nj & 1) << 1;
                    MMA16816(acc[mi][nj], ah[mi], bh[bq][hi], bh[bq][hi + 1]);
                    MMA16816(acc[mi][nj], al[mi], bh[bq][hi], bh[bq][hi + 1]);
                    MMA16816(acc[mi][nj], ah[mi], bl[bq][hi], bl[bq][hi + 1]);
                }
        }

        // Epilogue: mat 0 -> fp32 root (+bias); mats 1..8 -> fp16 msg blocks.
        if (mat == 0) {
#pragma unroll
            for (int mi = 0; mi < 2; mi++)
#pragma unroll
                for (int nj = 0; nj < 8; nj++) {
                    const int col = warpN + nj * 8 + tg * 2;
                    const float bx = bias ? bias[col] : 0.f;
                    const float by = bias ? bias[col + 1] : 0.f;
                    const int r0 = m0 + warpM + mi * 16 + g;
                    const int r1 = r0 + 8;
                    if (r0 < M)
                        *(float2*)(Croot + (size_t)r0 * DD + col) =
                            make_float2(acc[mi][nj][0] + bx, acc[mi][nj][1] + by);
                    if (r1 < M)
                        *(float2*)(Croot + (size_t)r1 * DD + col) =
                            make_float2(acc[mi][nj][2] + bx, acc[mi][nj][3] + by);
                }
        } else {
            const int cb = (mat - 1) * 128;
#pragma unroll
            for (int mi = 0; mi < 2; mi++)
#pragma unroll
                for (int nj = 0; nj < 8; nj++) {
                    const int col = warpN + nj * 8 + tg * 2;
                    const int r0 = m0 + warpM + mi * 16 + g;
                    const int r1 = r0 + 8;
                    if (r0 < M)
                        *(__half2*)(Cmsg + (size_t)r0 * MS + cb + col) =
                            __float22half2_rn(make_float2(acc[mi][nj][0], acc[mi][nj][1]));
                    if (r1 < M)
                        *(__half2*)(Cmsg + (size_t)r1 * MS + cb + col) =
                            __float22half2_rn(make_float2(acc[mi][nj][2], acc[mi][nj][3]));
                }
        }
    }
}

// ---------------------------------------------------------------------------
// Single-pass aggregation: one warp per dst.
// out[dst] = maybe_relu( root[dst] + sum_e msg[src_e][rel_e] * inv_cnt )
// Messages fp16, accumulation fp32. No atomics; each row written once.
// ---------------------------------------------------------------------------
static __device__ __forceinline__ float4 msg4(const __half* __restrict__ msg,
                                              int p, int c4) {
    const __half2* q = (const __half2*)(msg + (size_t)(p & 0x1FFFF) * MS
                                        + ((p >> 17) << 7) + c4);
    const float2 a = __half22float2(q[0]);
    const float2 b = __half22float2(q[1]);
    return make_float4(a.x, a.y, b.x, b.y);
}

__global__ void agg_k(const int* __restrict__ offd, const int* __restrict__ pack,
                      const int* __restrict__ cnt8, const float* __restrict__ root,
                      const __half* __restrict__ msg, float* __restrict__ out,
                      int E, int do_relu) {
    const int d = (blockIdx.x * blockDim.x + threadIdx.x) >> 5;
    if (d >= NN) return;
    const int lane = threadIdx.x & 31;
    const int lo = offd[d];
    const int hi = (d == NN - 1) ? E : offd[d + 1];

    float inv = 0.f;
    if (lane < RR) {
        int c = cnt8[d * RR + lane];
        inv = (c > 0) ? (1.0f / (float)c) : 0.f;
    }

    const int c4 = lane * 4;
    float4 acc = *(const float4*)(root + (size_t)d * DD + c4);

    int i = lo;
    for (; i + 4 <= hi; i += 4) {
        const int p0 = pack[i], p1 = pack[i + 1], p2 = pack[i + 2], p3 = pack[i + 3];
        const float4 v0 = msg4(msg, p0, c4);
        const float4 v1 = msg4(msg, p1, c4);
        const float4 v2 = msg4(msg, p2, c4);
        const float4 v3 = msg4(msg, p3, c4);
        const float i0 = __shfl_sync(~0u, inv, p0 >> 17);
        const float i1 = __shfl_sync(~0u, inv, p1 >> 17);
        const float i2 = __shfl_sync(~0u, inv, p2 >> 17);
        const float i3 = __shfl_sync(~0u, inv, p3 >> 17);
        acc.x += v0.x * i0 + v1.x * i1 + v2.x * i2 + v3.x * i3;
        acc.y += v0.y * i0 + v1.y * i1 + v2.y * i2 + v3.y * i3;
        acc.z += v0.z * i0 + v1.z * i1 + v2.z * i2 + v3.z * i3;
        acc.w += v0.w * i0 + v1.w * i1 + v2.w * i2 + v3.w * i3;
    }
    for (; i < hi; i++) {
        const int p = pack[i];
        const float4 v = msg4(msg, p, c4);
        const float iv = __shfl_sync(~0u, inv, p >> 17);
        acc.x += v.x * iv; acc.y += v.y * iv; acc.z += v.z * iv; acc.w += v.w * iv;
    }

    if (do_relu) {
        acc.x = fmaxf(acc.x, 0.f); acc.y = fmaxf(acc.y, 0.f);
        acc.z = fmaxf(acc.z, 0.f); acc.w = fmaxf(acc.w, 0.f);
    }
    *(float4*)(out + (size_t)d * DD + c4) = acc;
}

// ---------------------------------------------------------------------------
// Launch
// ---------------------------------------------------------------------------
extern "C" void kernel_launch(void* const* d_in, const int* in_sizes, int n_in,
                              void* d_out, int out_size) {
    const float* x     = (const float*)d_in[0];
    const int*   ei    = (const int*)d_in[1];
    const int*   et    = (const int*)d_in[2];
    const float* W1    = (const float*)d_in[3];
    const float* root1 = (const float*)d_in[4];
    const float* b1    = (const float*)d_in[5];
    const float* W2    = (const float*)d_in[6];
    const float* root2 = (const float*)d_in[7];
    const float* b2    = (const float*)d_in[8];
    float* out = (float*)d_out;

    const int E = in_sizes[1] / 2;
    const int N = in_sizes[0] / DD;

    float *rootb, *h;
    __half* msg;
    __nv_bfloat16 *wh, *wl;
    int *c8, *cd, *offd, *curd, *bsum, *pack;
    cudaGetSymbolAddress((void**)&rootb, g_root);
    cudaGetSymbolAddress((void**)&msg,   g_msg);
    cudaGetSymbolAddress((void**)&h,     g_h);
    cudaGetSymbolAddress((void**)&wh,    g_wh);
    cudaGetSymbolAddress((void**)&wl,    g_wl);
    cudaGetSymbolAddress((void**)&c8,    g_cnt8);
    cudaGetSymbolAddress((void**)&cd,    g_cntd);
    cudaGetSymbolAddress((void**)&offd,  g_offd);
    cudaGetSymbolAddress((void**)&curd,  g_curd);
    cudaGetSymbolAddress((void**)&bsum,  g_bsum);
    cudaGetSymbolAddress((void**)&pack,  g_pack);

    cudaFuncSetAttribute(gemm9_k, cudaFuncAttributeMaxDynamicSharedMemorySize, GSMEM);

    const int gemm_grid = (N + 127) / 128;
    const int agg_grid  = (NN * 32 + 255) / 256;
    const int nb = (NN + 1023) / 1024;

    detect_k<<<1, 256>>>(et, E);
    zero_cnt_k<<<(NN * RR + 255) / 256, 256>>>(c8, cd);
    count_k<<<(E + 255) / 256, 256>>>(ei, et, c8, cd, E);
    scan1_k<<<nb, 256>>>(cd, offd, bsum, NN);
    splitw9_k<<<(9 * DD * DD + 255) / 256, 256>>>(root1, W1, wh, wl);
    gemm9_k<<<gemm_grid, 256, GSMEM>>>(x, wh, wl, b1, rootb, msg, N);
    scan2_k<<<1, 1024>>>(bsum, nb);
    scan3_k<<<(NN + 255) / 256, 256>>>(offd, curd, bsum, NN);
    scatter_k<<<(E + 255) / 256, 256>>>(ei, et, curd, pack, E);
    agg_k<<<agg_grid, 256>>>(offd, pack, c8, rootb, msg, h, E, 1);

    splitw9_k<<<(9 * DD * DD + 255) / 256, 256>>>(root2, W2, wh, wl);
    gemm9_k<<<gemm_grid, 256, GSMEM>>>(h, wh, wl, b2, rootb, msg, N);
    agg_k<<<agg_grid, 256>>>(offd, pack, c8, rootb, msg, out, E, 0);
}

// round 9
// speedup vs baseline: 1.9022x; 1.0313x over previous
#include <cuda_runtime.h>
#include <cuda_bf16.h>
#include <cuda_fp16.h>
#include <cstdint>

#define NN 100000
#define EE 1600000
#define RR 8
#define DD 128
#define MS 1024            // msg row stride: 8 relations * 128 (fp16)

// ---------------------------------------------------------------------------
// Scratch (device globals; no allocation allowed anywhere).
// ---------------------------------------------------------------------------
__device__ __align__(16) float  g_root[(size_t)NN * DD];  // root part (fp32, bias folded)
__device__ __align__(16) __half g_msg[(size_t)NN * MS];   // relation blocks (fp16)
__device__ __align__(16) float  g_h [(size_t)NN * DD];    // hidden activations
__device__ __align__(16) __nv_bfloat16 g_wh[9 * DD * DD]; // [mat][n][k] weights hi
__device__ __align__(16) __nv_bfloat16 g_wl[9 * DD * DD]; // [mat][n][k] weights residual
__device__ int g_cnt8[NN * RR];   // per-(dst,rel) counts
__device__ int g_cntd[NN];        // per-dst counts
__device__ int g_offd[NN];        // exclusive dst offsets
__device__ int g_curd[NN];        // scatter cursors
__device__ int g_bsum[1024];      // scan block partials
__device__ int g_pack[EE];        // (rel<<17)|src, sorted by dst
__device__ int g_shift;           // 1 if edge arrays are int64, 0 if int32

// ---------------------------------------------------------------------------
// dtype autodetect (int64 edges => all odd 32-bit words zero)
// ---------------------------------------------------------------------------
__global__ void detect_k(const int* __restrict__ et, int E) {
    __shared__ int any;
    if (threadIdx.x == 0) any = 0;
    __syncthreads();
    int n = min(E, 4096);
    int local = 0;
    for (int i = threadIdx.x; i < n; i += blockDim.x) local |= et[2 * i + 1];
    if (local) atomicOr(&any, 1);
    __syncthreads();
    if (threadIdx.x == 0) g_shift = any ? 0 : 1;
}

// ---------------------------------------------------------------------------
// Counting sort by dst (rel packed into value)
// ---------------------------------------------------------------------------
__global__ void zero_cnt_k(int* __restrict__ c8, int* __restrict__ cd) {
    int i = blockIdx.x * blockDim.x + threadIdx.x;
    if (i < NN * RR) c8[i] = 0;
    if (i < NN) cd[i] = 0;
}
__global__ void count_k(const int* __restrict__ ei, const int* __restrict__ et,
                        int* __restrict__ c8, int* __restrict__ cd, int E) {
    int e = blockIdx.x * blockDim.x + threadIdx.x;
    if (e < E) {
        const int sh = g_shift;
        int d = ei[(E << sh) + (e << sh)];
        int r = et[e << sh];
        if ((unsigned)d < NN && (unsigned)r < RR) {
            atomicAdd(&c8[d * RR + r], 1);
            atomicAdd(&cd[d], 1);
        }
    }
}
__global__ void scan1_k(const int* __restrict__ cnt, int* __restrict__ off,
                        int* __restrict__ bsum, int M) {
    __shared__ int wsum[8];
    const int t = threadIdx.x;
    const int base = blockIdx.x * 1024 + t * 4;
    int v0 = 0, v1 = 0, v2 = 0, v3 = 0;
    if (base + 0 < M) v0 = cnt[base + 0];
    if (base + 1 < M) v1 = cnt[base + 1];
    if (base + 2 < M) v2 = cnt[base + 2];
    if (base + 3 < M) v3 = cnt[base + 3];
    const int tsum = v0 + v1 + v2 + v3;
    const int lane = t & 31, wid = t >> 5;
    int x = tsum;
#pragma unroll
    for (int o = 1; o < 32; o <<= 1) {
        int y = __shfl_up_sync(~0u, x, o);
        if (lane >= o) x += y;
    }
    if (lane == 31) wsum[wid] = x;
    __syncthreads();
    if (wid == 0) {
        int w = (lane < 8) ? wsum[lane] : 0;
#pragma unroll
        for (int o = 1; o < 8; o <<= 1) {
            int y = __shfl_up_sync(~0u, w, o);
            if (lane >= o) w += y;
        }
        if (lane < 8) wsum[lane] = w;
    }
    __syncthreads();
    const int excl = x - tsum + (wid > 0 ? wsum[wid - 1] : 0);
    if (base + 0 < M) off[base + 0] = excl;
    if (base + 1 < M) off[base + 1] = excl + v0;
    if (base + 2 < M) off[base + 2] = excl + v0 + v1;
    if (base + 3 < M) off[base + 3] = excl + v0 + v1 + v2;
    if (t == 0) bsum[blockIdx.x] = wsum[7];
}
__global__ void scan2_k(int* __restrict__ bsum, int nb) {
    __shared__ int sh[1024];
    const int t = threadIdx.x;
    sh[t] = (t < nb) ? bsum[t] : 0;
    __syncthreads();
    for (int o = 1; o < 1024; o <<= 1) {
        int v = (t >= o) ? sh[t - o] : 0;
        __syncthreads();
        sh[t] += v;
        __syncthreads();
    }
    if (t < nb) bsum[t] = (t == 0) ? 0 : sh[t - 1];
}
__global__ void scan3_k(int* __restrict__ off, int* __restrict__ cur,
                        const int* __restrict__ bsum, int M) {
    int i = blockIdx.x * blockDim.x + threadIdx.x;
    if (i < M) {
        int v = off[i] + bsum[i >> 10];
        off[i] = v;
        cur[i] = v;
    }
}
__global__ void scatter_k(const int* __restrict__ ei, const int* __restrict__ et,
                          int* __restrict__ cur, int* __restrict__ pack, int E) {
    int e = blockIdx.x * blockDim.x + threadIdx.x;
    if (e < E) {
        const int sh = g_shift;
        int s = ei[e << sh];
        int d = ei[(E << sh) + (e << sh)];
        int r = et[e << sh];
        if ((unsigned)d < NN && (unsigned)r < RR && (unsigned)s < NN) {
            int pos = atomicAdd(&cur[d], 1);
            pack[pos] = (r << 17) | s;
        }
    }
}

// ---------------------------------------------------------------------------
// Weight transpose + split: out[mat][n][k], mat 0 = root, 1..8 = W[r]
// ---------------------------------------------------------------------------
__global__ void splitw9_k(const float* __restrict__ root, const float* __restrict__ W,
                          __nv_bfloat16* __restrict__ H, __nv_bfloat16* __restrict__ L) {
    int idx = blockIdx.x * blockDim.x + threadIdx.x;
    if (idx < 9 * DD * DD) {
        int mat = idx >> 14;
        int rem = idx & 16383;
        int n = rem >> 7;
        int k = rem & 127;
        float v = (mat == 0) ? root[(k << 7) + n] : W[((mat - 1) << 14) + (k << 7) + n];
        __nv_bfloat16 h = __float2bfloat16(v);
        __nv_bfloat16 l = __float2bfloat16(v - __bfloat162float(h));
        H[idx] = h;
        L[idx] = l;
    }
}

// ---------------------------------------------------------------------------
// Batched tensor-core GEMM, 384 threads (12 warps, 3/SMSP), tile M=192 x N=128.
// A (bf16 hi+lo) smem-resident; B streamed as 18 k-half chunks (9 mats x 2)
// through a 3-stage cp.async ring -> B-load latency hidden at mat boundaries.
// Outputs: mat 0 -> fp32 root (+bias); mats 1..8 -> fp16 msg blocks.
// ---------------------------------------------------------------------------
#define TM 192
#define NTHR 384
#define SSTR 136                          // A row stride (bf16 elems)
#define A_TILE (TM * SSTR * 2)            // 52224 bytes per precision
#define BSTR 72                           // B chunk row stride (64 data + 8 pad)
#define B_STAGE (128 * BSTR * 2 * 2)      // h+l per stage = 36864 bytes
#define GSMEM (2 * A_TILE + 3 * B_STAGE)  // 104448 + 110592 = 215040

static __device__ __forceinline__ uint32_t smem_u32(const void* p) {
    uint32_t a;
    asm("{ .reg .u64 t; cvta.to.shared.u64 t, %1; cvt.u32.u64 %0, t; }"
        : "=r"(a) : "l"(p));
    return a;
}
#define LDSM_X4(r0, r1, r2, r3, addr) \
    asm volatile("ldmatrix.sync.aligned.m8n8.x4.shared.b16 {%0,%1,%2,%3}, [%4];" \
                 : "=r"(r0), "=r"(r1), "=r"(r2), "=r"(r3) : "r"(addr))
#define MMA16816(d, a, b0, b1) \
    asm volatile("mma.sync.aligned.m16n8k16.row.col.f32.bf16.bf16.f32 " \
                 "{%0,%1,%2,%3}, {%4,%5,%6,%7}, {%8,%9}, {%0,%1,%2,%3};" \
                 : "+f"((d)[0]), "+f"((d)[1]), "+f"((d)[2]), "+f"((d)[3]) \
                 : "r"((a)[0]), "r"((a)[1]), "r"((a)[2]), "r"((a)[3]), \
                   "r"(b0), "r"(b1))
#define CP_ASYNC16(saddr, gptr) \
    asm volatile("cp.async.cg.shared.global [%0], [%1], 16;" \
                 :: "r"(saddr), "l"(gptr))

// Load one k-half chunk (mat = chunk>>1, k0 = (chunk&1)*64) into ring stage.
static __device__ __forceinline__ void prefetch_chunk(
    const __nv_bfloat16* __restrict__ Wh, const __nv_bfloat16* __restrict__ Wl,
    uint32_t uStage, int chunk, int t) {
    const int mat = chunk >> 1;
    const int k0  = (chunk & 1) << 6;
    const __nv_bfloat16* bh = Wh + (size_t)mat * DD * DD + k0;
    const __nv_bfloat16* bl = Wl + (size_t)mat * DD * DD + k0;
    const uint32_t uH = uStage;
    const uint32_t uL = uStage + 128 * BSTR * 2;
    // 128 rows x 64 bf16 = 8 chunks of 16B per row -> 1024 per precision
#pragma unroll
    for (int it = 0; it < 3; it++) {
        const int idx = it * NTHR + t;
        if (idx < 1024) {
            const int row = idx >> 3;
            const int c16 = (idx & 7) * 8;
            const uint32_t soff = (uint32_t)(row * BSTR + c16) * 2;
            CP_ASYNC16(uH + soff, bh + row * DD + c16);
            CP_ASYNC16(uL + soff, bl + row * DD + c16);
        }
    }
}

__global__ void __launch_bounds__(NTHR, 1)
gemm9_k(const float* __restrict__ A, const __nv_bfloat16* __restrict__ Wh,
        const __nv_bfloat16* __restrict__ Wl, const float* __restrict__ bias,
        float* __restrict__ Croot, __half* __restrict__ Cmsg, int M) {
    extern __shared__ char smc[];
    __nv_bfloat16* sAh = (__nv_bfloat16*)smc;
    __nv_bfloat16* sAl = (__nv_bfloat16*)(smc + A_TILE);
    const uint32_t uAh = smem_u32(sAh), uAl = smem_u32(sAl);
    const uint32_t uB  = uAh + 2 * A_TILE;   // 3 stages of B_STAGE

    const int t   = threadIdx.x;
    const int wid = t >> 5, lid = t & 31;
    const int m0  = blockIdx.x * TM;

    // Kick off the first two B chunks; they overlap the A load+split.
    prefetch_chunk(Wh, Wl, uB + 0 * B_STAGE, 0, t);
    asm volatile("cp.async.commit_group;");
    prefetch_chunk(Wh, Wl, uB + 1 * B_STAGE, 1, t);
    asm volatile("cp.async.commit_group;");

    // A tile: read fp32, split to bf16 hi/residual in registers, store smem.
    // 192 rows x 32 float4-chunks = 6144, 384 threads -> 16 iters.
#pragma unroll
    for (int it = 0; it < 16; it++) {
        const int idx = it * NTHR + t;
        const int row = idx >> 5;
        const int c4  = (idx & 31) * 4;
        float4 v = make_float4(0.f, 0.f, 0.f, 0.f);
        const int gr = m0 + row;
        if (gr < M) v = *(const float4*)(A + (size_t)gr * DD + c4);
        __nv_bfloat162 h01 = __floats2bfloat162_rn(v.x, v.y);
        __nv_bfloat162 h23 = __floats2bfloat162_rn(v.z, v.w);
        __nv_bfloat162 l01 = __floats2bfloat162_rn(v.x - __bfloat162float(h01.x),
                                                   v.y - __bfloat162float(h01.y));
        __nv_bfloat162 l23 = __floats2bfloat162_rn(v.z - __bfloat162float(h23.x),
                                                   v.w - __bfloat162float(h23.y));
        const int soff = row * SSTR + c4;
        *(__nv_bfloat162*)(sAh + soff)     = h01;
        *(__nv_bfloat162*)(sAh + soff + 2) = h23;
        *(__nv_bfloat162*)(sAl + soff)     = l01;
        *(__nv_bfloat162*)(sAl + soff + 2) = l23;
    }

    // Warp layout: 6 (m) x 2 (n); warp tile 32(m) x 64(n).
    const int warpM = (wid % 6) * 32;
    const int warpN = (wid / 6) * 64;
    const int aRow = warpM + (lid & 15);
    const int aK   = (lid >> 4) << 3;
    const int bN   = warpN + (lid & 7) + ((lid >> 4) << 3);
    const int bK   = ((lid >> 3) & 1) << 3;
    const int g    = lid >> 2;
    const int tg   = lid & 3;

    float acc[2][8][4];
#pragma unroll
    for (int i = 0; i < 2; i++)
#pragma unroll
        for (int j = 0; j < 8; j++)
#pragma unroll
            for (int c = 0; c < 4; c++) acc[i][j][c] = 0.0f;

    for (int chunk = 0; chunk < 18; chunk++) {
        // All warps finished reading stage[(chunk-1)%3] (compute of chunk-1
        // completed before we got here); safe to overwrite it with chunk+2.
        __syncthreads();
        if (chunk + 2 < 18) {
            prefetch_chunk(Wh, Wl, uB + ((chunk + 2) % 3) * B_STAGE, chunk + 2, t);
            asm volatile("cp.async.commit_group;");
        }
        // Groups committed: min(chunk+3, 18). Need group 'chunk' complete.
        if (chunk < 16)      asm volatile("cp.async.wait_group 2;");
        else if (chunk == 16) asm volatile("cp.async.wait_group 1;");
        else                  asm volatile("cp.async.wait_group 0;");
        __syncthreads();   // chunk's stage visible to all warps

        const uint32_t ubh = uB + (chunk % 3) * B_STAGE;
        const uint32_t ubl = ubh + 128 * BSTR * 2;
        const int kbase = (chunk & 1) << 6;  // k offset within A (0 or 64)

#pragma unroll
        for (int ks = 0; ks < 4; ks++) {
            const int kA = kbase + ks * 16;   // A k index
            const int kB = ks * 16;           // B k index within chunk
            uint32_t ah[2][4], al[2][4];
#pragma unroll
            for (int mi = 0; mi < 2; mi++) {
                const uint32_t ao = (uint32_t)(((aRow + mi * 16) * SSTR + (aK + kA)) * 2);
                LDSM_X4(ah[mi][0], ah[mi][1], ah[mi][2], ah[mi][3], uAh + ao);
                LDSM_X4(al[mi][0], al[mi][1], al[mi][2], al[mi][3], uAl + ao);
            }
            uint32_t bh[4][4], bl[4][4];
#pragma unroll
            for (int bq = 0; bq < 4; bq++) {
                const uint32_t bo = (uint32_t)(((bN + bq * 16) * BSTR + (bK + kB)) * 2);
                LDSM_X4(bh[bq][0], bh[bq][1], bh[bq][2], bh[bq][3], ubh + bo);
                LDSM_X4(bl[bq][0], bl[bq][1], bl[bq][2], bl[bq][3], ubl + bo);
            }
#pragma unroll
            for (int mi = 0; mi < 2; mi++)
#pragma unroll
                for (int nj = 0; nj < 8; nj++) {
                    const int bq = nj >> 1, hi = (nj & 1) << 1;
                    MMA16816(acc[mi][nj], ah[mi], bh[bq][hi], bh[bq][hi + 1]);
                    MMA16816(acc[mi][nj], al[mi], bh[bq][hi], bh[bq][hi + 1]);
                    MMA16816(acc[mi][nj], ah[mi], bl[bq][hi], bl[bq][hi + 1]);
                }
        }

        if (chunk & 1) {
            // Mat finished -> epilogue, then clear accumulators.
            const int mat = chunk >> 1;
            if (mat == 0) {
#pragma unroll
                for (int mi = 0; mi < 2; mi++)
#pragma unroll
                    for (int nj = 0; nj < 8; nj++) {
                        const int col = warpN + nj * 8 + tg * 2;
                        const float bx = bias ? bias[col] : 0.f;
                        const float by = bias ? bias[col + 1] : 0.f;
                        const int r0 = m0 + warpM + mi * 16 + g;
                        const int r1 = r0 + 8;
                        if (r0 < M)
                            *(float2*)(Croot + (size_t)r0 * DD + col) =
                                make_float2(acc[mi][nj][0] + bx, acc[mi][nj][1] + by);
                        if (r1 < M)
                            *(float2*)(Croot + (size_t)r1 * DD + col) =
                                make_float2(acc[mi][nj][2] + bx, acc[mi][nj][3] + by);
                    }
            } else {
                const int cb = (mat - 1) * 128;
#pragma unroll
                for (int mi = 0; mi < 2; mi++)
#pragma unroll
                    for (int nj = 0; nj < 8; nj++) {
                        const int col = warpN + nj * 8 + tg * 2;
                        const int r0 = m0 + warpM + mi * 16 + g;
                        const int r1 = r0 + 8;
                        if (r0 < M)
                            *(__half2*)(Cmsg + (size_t)r0 * MS + cb + col) =
                                __float22half2_rn(make_float2(acc[mi][nj][0], acc[mi][nj][1]));
                        if (r1 < M)
                            *(__half2*)(Cmsg + (size_t)r1 * MS + cb + col) =
                                __float22half2_rn(make_float2(acc[mi][nj][2], acc[mi][nj][3]));
                    }
            }
#pragma unroll
            for (int i = 0; i < 2; i++)
#pragma unroll
                for (int j = 0; j < 8; j++)
#pragma unroll
                    for (int c = 0; c < 4; c++) acc[i][j][c] = 0.0f;
        }
    }
}

// ---------------------------------------------------------------------------
// Single-pass aggregation: one warp per dst.
// out[dst] = maybe_relu( root[dst] + sum_e msg[src_e][rel_e] * inv_cnt )
// Messages fp16, accumulation fp32. No atomics; each row written once.
// ---------------------------------------------------------------------------
static __device__ __forceinline__ float4 msg4(const __half* __restrict__ msg,
                                              int p, int c4) {
    const __half2* q = (const __half2*)(msg + (size_t)(p & 0x1FFFF) * MS
                                        + ((p >> 17) << 7) + c4);
    const float2 a = __half22float2(q[0]);
    const float2 b = __half22float2(q[1]);
    return make_float4(a.x, a.y, b.x, b.y);
}

__global__ void agg_k(const int* __restrict__ offd, const int* __restrict__ pack,
                      const int* __restrict__ cnt8, const float* __restrict__ root,
                      const __half* __restrict__ msg, float* __restrict__ out,
                      int E, int do_relu) {
    const int d = (blockIdx.x * blockDim.x + threadIdx.x) >> 5;
    if (d >= NN) return;
    const int lane = threadIdx.x & 31;
    const int lo = offd[d];
    const int hi = (d == NN - 1) ? E : offd[d + 1];

    float inv = 0.f;
    if (lane < RR) {
        int c = cnt8[d * RR + lane];
        inv = (c > 0) ? (1.0f / (float)c) : 0.f;
    }

    const int c4 = lane * 4;
    float4 acc = *(const float4*)(root + (size_t)d * DD + c4);

    int i = lo;
    for (; i + 4 <= hi; i += 4) {
        const int p0 = pack[i], p1 = pack[i + 1], p2 = pack[i + 2], p3 = pack[i + 3];
        const float4 v0 = msg4(msg, p0, c4);
        const float4 v1 = msg4(msg, p1, c4);
        const float4 v2 = msg4(msg, p2, c4);
        const float4 v3 = msg4(msg, p3, c4);
        const float i0 = __shfl_sync(~0u, inv, p0 >> 17);
        const float i1 = __shfl_sync(~0u, inv, p1 >> 17);
        const float i2 = __shfl_sync(~0u, inv, p2 >> 17);
        const float i3 = __shfl_sync(~0u, inv, p3 >> 17);
        acc.x += v0.x * i0 + v1.x * i1 + v2.x * i2 + v3.x * i3;
        acc.y += v0.y * i0 + v1.y * i1 + v2.y * i2 + v3.y * i3;
        acc.z += v0.z * i0 + v1.z * i1 + v2.z * i2 + v3.z * i3;
        acc.w += v0.w * i0 + v1.w * i1 + v2.w * i2 + v3.w * i3;
    }
    for (; i < hi; i++) {
        const int p = pack[i];
        const float4 v = msg4(msg, p, c4);
        const float iv = __shfl_sync(~0u, inv, p >> 17);
        acc.x += v.x * iv; acc.y += v.y * iv; acc.z += v.z * iv; acc.w += v.w * iv;
    }

    if (do_relu) {
        acc.x = fmaxf(acc.x, 0.f); acc.y = fmaxf(acc.y, 0.f);
        acc.z = fmaxf(acc.z, 0.f); acc.w = fmaxf(acc.w, 0.f);
    }
    *(float4*)(out + (size_t)d * DD + c4) = acc;
}

// ---------------------------------------------------------------------------
// Launch
// ---------------------------------------------------------------------------
extern "C" void kernel_launch(void* const* d_in, const int* in_sizes, int n_in,
                              void* d_out, int out_size) {
    const float* x     = (const float*)d_in[0];
    const int*   ei    = (const int*)d_in[1];
    const int*   et    = (const int*)d_in[2];
    const float* W1    = (const float*)d_in[3];
    const float* root1 = (const float*)d_in[4];
    const float* b1    = (const float*)d_in[5];
    const float* W2    = (const float*)d_in[6];
    const float* root2 = (const float*)d_in[7];
    const float* b2    = (const float*)d_in[8];
    float* out = (float*)d_out;

    const int E = in_sizes[1] / 2;
    const int N = in_sizes[0] / DD;

    float *rootb, *h;
    __half* msg;
    __nv_bfloat16 *wh, *wl;
    int *c8, *cd, *offd, *curd, *bsum, *pack;
    cudaGetSymbolAddress((void**)&rootb, g_root);
    cudaGetSymbolAddress((void**)&msg,   g_msg);
    cudaGetSymbolAddress((void**)&h,     g_h);
    cudaGetSymbolAddress((void**)&wh,    g_wh);
    cudaGetSymbolAddress((void**)&wl,    g_wl);
    cudaGetSymbolAddress((void**)&c8,    g_cnt8);
    cudaGetSymbolAddress((void**)&cd,    g_cntd);
    cudaGetSymbolAddress((void**)&offd,  g_offd);
    cudaGetSymbolAddress((void**)&curd,  g_curd);
    cudaGetSymbolAddress((void**)&bsum,  g_bsum);
    cudaGetSymbolAddress((void**)&pack,  g_pack);

    cudaFuncSetAttribute(gemm9_k, cudaFuncAttributeMaxDynamicSharedMemorySize, GSMEM);

    const int gemm_grid = (N + TM - 1) / TM;
    const int agg_grid  = (NN * 32 + 255) / 256;
    const int nb = (NN + 1023) / 1024;

    detect_k<<<1, 256>>>(et, E);
    zero_cnt_k<<<(NN * RR + 255) / 256, 256>>>(c8, cd);
    count_k<<<(E + 255) / 256, 256>>>(ei, et, c8, cd, E);
    scan1_k<<<nb, 256>>>(cd, offd, bsum, NN);
    splitw9_k<<<(9 * DD * DD + 255) / 256, 256>>>(root1, W1, wh, wl);
    gemm9_k<<<gemm_grid, NTHR, GSMEM>>>(x, wh, wl, b1, rootb, msg, N);
    scan2_k<<<1, 1024>>>(bsum, nb);
    scan3_k<<<(NN + 255) / 256, 256>>>(offd, curd, bsum, NN);
    scatter_k<<<(E + 255) / 256, 256>>>(ei, et, curd, pack, E);
    agg_k<<<agg_grid, 256>>>(offd, pack, c8, rootb, msg, h, E, 1);

    splitw9_k<<<(9 * DD * DD + 255) / 256, 256>>>(root2, W2, wh, wl);
    gemm9_k<<<gemm_grid, NTHR, GSMEM>>>(h, wh, wl, b2, rootb, msg, N);
    agg_k<<<agg_grid, 256>>>(offd, pack, c8, rootb, msg, out, E, 0);
}

// round 10
// speedup vs baseline: 2.4998x; 1.3142x over previous
#include <cuda_runtime.h>
#include <cuda_fp16.h>
#include <cstdint>

#define NN 100000
#define EE 1600000
#define RR 8
#define DD 128
#define M8 (NN * RR)       // sort bins, key = dst*8 + rel

// ---------------------------------------------------------------------------
// Scratch (device globals; no allocation allowed anywhere).
// ---------------------------------------------------------------------------
__device__ __align__(16) __half g_x16[(size_t)NN * DD];        // fp16 features (layer in)
__device__ __align__(16) __half g_h16[(size_t)NN * DD];        // fp16 hidden
__device__ __align__(16) __half g_xbar[(size_t)NN * RR * DD];  // per-(dst,rel) means
__device__ __align__(16) __half g_wh[9 * DD * DD];  // [mat][n][k] weights fp16 hi
__device__ __align__(16) __half g_wl[9 * DD * DD];  // [mat][n][k] weights fp16 lo
__device__ int g_cnt[M8];
__device__ int g_off[M8];
__device__ int g_cur[M8];
__device__ int g_bsum[1024];
__device__ int g_pack[EE];     // src ids, sorted by (dst,rel)
__device__ int g_shift;        // 1 if edge arrays are int64, 0 if int32

// ---------------------------------------------------------------------------
// dtype autodetect (int64 edges => all odd 32-bit words zero)
// ---------------------------------------------------------------------------
__global__ void detect_k(const int* __restrict__ et, int E) {
    __shared__ int any;
    if (threadIdx.x == 0) any = 0;
    __syncthreads();
    int n = min(E, 4096);
    int local = 0;
    for (int i = threadIdx.x; i < n; i += blockDim.x) local |= et[2 * i + 1];
    if (local) atomicOr(&any, 1);
    __syncthreads();
    if (threadIdx.x == 0) g_shift = any ? 0 : 1;
}

// ---------------------------------------------------------------------------
// Counting sort by key (dst*8 + rel)
// ---------------------------------------------------------------------------
__global__ void zero_cnt_k(int* __restrict__ c) {
    int i = blockIdx.x * blockDim.x + threadIdx.x;
    if (i < M8) c[i] = 0;
}
__global__ void count_k(const int* __restrict__ ei, const int* __restrict__ et,
                        int* __restrict__ cnt, int E) {
    int e = blockIdx.x * blockDim.x + threadIdx.x;
    if (e < E) {
        const int sh = g_shift;
        int d = ei[(E << sh) + (e << sh)];
        int r = et[e << sh];
        if ((unsigned)d < NN && (unsigned)r < RR)
            atomicAdd(&cnt[d * RR + r], 1);
    }
}
__global__ void scan1_k(const int* __restrict__ cnt, int* __restrict__ off,
                        int* __restrict__ bsum, int M) {
    __shared__ int wsum[8];
    const int t = threadIdx.x;
    const int base = blockIdx.x * 1024 + t * 4;
    int v0 = 0, v1 = 0, v2 = 0, v3 = 0;
    if (base + 0 < M) v0 = cnt[base + 0];
    if (base + 1 < M) v1 = cnt[base + 1];
    if (base + 2 < M) v2 = cnt[base + 2];
    if (base + 3 < M) v3 = cnt[base + 3];
    const int tsum = v0 + v1 + v2 + v3;
    const int lane = t & 31, wid = t >> 5;
    int x = tsum;
#pragma unroll
    for (int o = 1; o < 32; o <<= 1) {
        int y = __shfl_up_sync(~0u, x, o);
        if (lane >= o) x += y;
    }
    if (lane == 31) wsum[wid] = x;
    __syncthreads();
    if (wid == 0) {
        int w = (lane < 8) ? wsum[lane] : 0;
#pragma unroll
        for (int o = 1; o < 8; o <<= 1) {
            int y = __shfl_up_sync(~0u, w, o);
            if (lane >= o) w += y;
        }
        if (lane < 8) wsum[lane] = w;
    }
    __syncthreads();
    const int excl = x - tsum + (wid > 0 ? wsum[wid - 1] : 0);
    if (base + 0 < M) off[base + 0] = excl;
    if (base + 1 < M) off[base + 1] = excl + v0;
    if (base + 2 < M) off[base + 2] = excl + v0 + v1;
    if (base + 3 < M) off[base + 3] = excl + v0 + v1 + v2;
    if (t == 0) bsum[blockIdx.x] = wsum[7];
}
__global__ void scan2_k(int* __restrict__ bsum, int nb) {
    __shared__ int sh[1024];
    const int t = threadIdx.x;
    sh[t] = (t < nb) ? bsum[t] : 0;
    __syncthreads();
    for (int o = 1; o < 1024; o <<= 1) {
        int v = (t >= o) ? sh[t - o] : 0;
        __syncthreads();
        sh[t] += v;
        __syncthreads();
    }
    if (t < nb) bsum[t] = (t == 0) ? 0 : sh[t - 1];
}
__global__ void scan3_k(int* __restrict__ off, int* __restrict__ cur,
                        const int* __restrict__ bsum, int M) {
    int i = blockIdx.x * blockDim.x + threadIdx.x;
    if (i < M) {
        int v = off[i] + bsum[i >> 10];
        off[i] = v;
        cur[i] = v;
    }
}
__global__ void scatter_k(const int* __restrict__ ei, const int* __restrict__ et,
                          int* __restrict__ cur, int* __restrict__ pack, int E) {
    int e = blockIdx.x * blockDim.x + threadIdx.x;
    if (e < E) {
        const int sh = g_shift;
        int s = ei[e << sh];
        int d = ei[(E << sh) + (e << sh)];
        int r = et[e << sh];
        if ((unsigned)d < NN && (unsigned)r < RR && (unsigned)s < NN) {
            int pos = atomicAdd(&cur[d * RR + r], 1);
            pack[pos] = s;
        }
    }
}

// ---------------------------------------------------------------------------
// fp32 -> fp16 feature conversion
// ---------------------------------------------------------------------------
__global__ void cvt16_k(const float* __restrict__ A, __half* __restrict__ B, size_t n4) {
    size_t i = (size_t)blockIdx.x * blockDim.x + threadIdx.x;
    if (i < n4) {
        float4 v = ((const float4*)A)[i];
        __half2 a = __float22half2_rn(make_float2(v.x, v.y));
        __half2 b = __float22half2_rn(make_float2(v.z, v.w));
        ((__half2*)B)[2 * i]     = a;
        ((__half2*)B)[2 * i + 1] = b;
    }
}

// ---------------------------------------------------------------------------
// Weight transpose + split to fp16 hi/lo: out[mat][n][k]; mat0=root, 1..8=W[r]
// ---------------------------------------------------------------------------
__global__ void splitw9_k(const float* __restrict__ root, const float* __restrict__ W,
                          __half* __restrict__ H, __half* __restrict__ L) {
    int idx = blockIdx.x * blockDim.x + threadIdx.x;
    if (idx < 9 * DD * DD) {
        int mat = idx >> 14;
        int rem = idx & 16383;
        int n = rem >> 7;
        int k = rem & 127;
        float v = (mat == 0) ? root[(k << 7) + n] : W[((mat - 1) << 14) + (k << 7) + n];
        __half h = __float2half_rn(v);
        __half l = __float2half_rn(v - __half2float(h));
        H[idx] = h;
        L[idx] = l;
    }
}

// ---------------------------------------------------------------------------
// Gather-mean: xbar[d][r] = mean over edges (sorted (dst,rel)) of src16[src].
// One warp per dst; gathers hit the 25.6MB L2-resident fp16 feature buffer.
// ---------------------------------------------------------------------------
__global__ void aggx_k(const int* __restrict__ off, const int* __restrict__ pack,
                       const __half* __restrict__ src16, __half* __restrict__ xbar,
                       int E) {
    const int d = (blockIdx.x * blockDim.x + threadIdx.x) >> 5;
    if (d >= NN) return;
    const int lane = threadIdx.x & 31;
    const int base = d * RR;

    int v = E;
    if (lane < 9 && base + lane < M8) v = off[base + lane];

    const int c4 = lane * 4;
#pragma unroll
    for (int r = 0; r < RR; r++) {
        const int lo = __shfl_sync(~0u, v, r);
        const int hi = __shfl_sync(~0u, v, r + 1);
        float4 acc = make_float4(0.f, 0.f, 0.f, 0.f);
        int i = lo;
        for (; i + 2 <= hi; i += 2) {
            const int s0 = pack[i], s1 = pack[i + 1];
            const float2 q0 = *(const float2*)(src16 + (size_t)s0 * DD + c4);
            const float2 q1 = *(const float2*)(src16 + (size_t)s1 * DD + c4);
            const __half2 a0 = *(const __half2*)&q0.x, b0 = *(const __half2*)&q0.y;
            const __half2 a1 = *(const __half2*)&q1.x, b1 = *(const __half2*)&q1.y;
            float2 f;
            f = __half22float2(a0); acc.x += f.x; acc.y += f.y;
            f = __half22float2(b0); acc.z += f.x; acc.w += f.y;
            f = __half22float2(a1); acc.x += f.x; acc.y += f.y;
            f = __half22float2(b1); acc.z += f.x; acc.w += f.y;
        }
        for (; i < hi; i++) {
            const int s = pack[i];
            const float2 q = *(const float2*)(src16 + (size_t)s * DD + c4);
            const __half2 a = *(const __half2*)&q.x, b = *(const __half2*)&q.y;
            float2 f;
            f = __half22float2(a); acc.x += f.x; acc.y += f.y;
            f = __half22float2(b); acc.z += f.x; acc.w += f.y;
        }
        const float inv = (hi > lo) ? (1.0f / (float)(hi - lo)) : 0.f;
        __half2 o0 = __float22half2_rn(make_float2(acc.x * inv, acc.y * inv));
        __half2 o1 = __float22half2_rn(make_float2(acc.z * inv, acc.w * inv));
        float2 ov;
        *(__half2*)&ov.x = o0;
        *(__half2*)&ov.y = o1;
        *(float2*)(xbar + ((size_t)base + r) * DD + c4) = ov;
    }
}

// ---------------------------------------------------------------------------
// K=1152 GEMM: out = act( concat(x16, xbar_0..7)[M,1152] @ Wcat[1152,128] + b )
// 384 threads, tile M=192 x N=128. 18 k-half chunks (9 mats x 2 halves of 64)
// through a 3-stage cp.async ring (A fp16 + B fp16 h/l per stage).
// 2 MMA passes: A*(Wh) + A*(Wl). Single accumulator, single fused epilogue.
// ---------------------------------------------------------------------------
#define TM 192
#define NTHR 384
#define CH 72                            // chunk row stride (64 data + 8 pad)
#define A_ST (TM * CH * 2)               // 27648
#define B_ST (128 * CH * 2 * 2)          // 36864 (h + l)
#define STAGE (A_ST + B_ST)              // 64512
#define GSMEM (3 * STAGE)                // 193536

static __device__ __forceinline__ uint32_t smem_u32(const void* p) {
    uint32_t a;
    asm("{ .reg .u64 t; cvta.to.shared.u64 t, %1; cvt.u32.u64 %0, t; }"
        : "=r"(a) : "l"(p));
    return a;
}
#define LDSM_X4(r0, r1, r2, r3, addr) \
    asm volatile("ldmatrix.sync.aligned.m8n8.x4.shared.b16 {%0,%1,%2,%3}, [%4];" \
                 : "=r"(r0), "=r"(r1), "=r"(r2), "=r"(r3) : "r"(addr))
#define MMAF16(d, a, b0, b1) \
    asm volatile("mma.sync.aligned.m16n8k16.row.col.f32.f16.f16.f32 " \
                 "{%0,%1,%2,%3}, {%4,%5,%6,%7}, {%8,%9}, {%0,%1,%2,%3};" \
                 : "+f"((d)[0]), "+f"((d)[1]), "+f"((d)[2]), "+f"((d)[3]) \
                 : "r"((a)[0]), "r"((a)[1]), "r"((a)[2]), "r"((a)[3]), \
                   "r"(b0), "r"(b1))
#define CP_ASYNC16Z(saddr, gptr, sz) \
    asm volatile("cp.async.cg.shared.global [%0], [%1], 16, %2;" \
                 :: "r"(saddr), "l"(gptr), "r"(sz))
#define CP_ASYNC16(saddr, gptr) \
    asm volatile("cp.async.cg.shared.global [%0], [%1], 16;" \
                 :: "r"(saddr), "l"(gptr))

static __device__ __forceinline__ void prefetch_chunk(
    const __half* __restrict__ X16, const __half* __restrict__ XB,
    const __half* __restrict__ Wh, const __half* __restrict__ Wl,
    uint32_t uStage, int chunk, int t, int m0, int M) {
    const int mat = chunk >> 1;
    const int k0  = (chunk & 1) << 6;
    // --- A: 192 rows x 64 halves = 8 x 16B per row -> 1536 ops, 4 iters ---
    const uint32_t uA = uStage;
#pragma unroll
    for (int it = 0; it < 4; it++) {
        const int idx = it * NTHR + t;
        const int row = idx >> 3;
        const int c16 = (idx & 7) * 8;
        const int gr  = m0 + row;
        const int ok  = (gr < M);
        const int grc = ok ? gr : (M - 1);
        const __half* ap = (mat == 0)
            ? X16 + (size_t)grc * DD + k0 + c16
            : XB  + ((size_t)grc * RR + (mat - 1)) * DD + k0 + c16;
        CP_ASYNC16Z(uA + (uint32_t)(row * CH + c16) * 2, ap, ok ? 16 : 0);
    }
    // --- B: 128 rows x 64 halves, h + l -> 1024 ops each, 3 iters each ---
    const __half* bh = Wh + (size_t)mat * DD * DD + k0;
    const __half* bl = Wl + (size_t)mat * DD * DD + k0;
    const uint32_t uH = uStage + A_ST;
    const uint32_t uL = uH + 128 * CH * 2;
#pragma unroll
    for (int it = 0; it < 3; it++) {
        const int idx = it * NTHR + t;
        if (idx < 1024) {
            const int row = idx >> 3;
            const int c16 = (idx & 7) * 8;
            const uint32_t soff = (uint32_t)(row * CH + c16) * 2;
            CP_ASYNC16(uH + soff, bh + row * DD + c16);
            CP_ASYNC16(uL + soff, bl + row * DD + c16);
        }
    }
}

__global__ void __launch_bounds__(NTHR, 1)
gemmK_k(const __half* __restrict__ X16, const __half* __restrict__ XB,
        const __half* __restrict__ Wh, const __half* __restrict__ Wl,
        const float* __restrict__ bias, float* __restrict__ outF,
        __half* __restrict__ outH, int M) {
    extern __shared__ char smc[];
    const uint32_t uS = smem_u32(smc);

    const int t   = threadIdx.x;
    const int wid = t >> 5, lid = t & 31;
    const int m0  = blockIdx.x * TM;

    prefetch_chunk(X16, XB, Wh, Wl, uS + 0 * STAGE, 0, t, m0, M);
    asm volatile("cp.async.commit_group;");
    prefetch_chunk(X16, XB, Wh, Wl, uS + 1 * STAGE, 1, t, m0, M);
    asm volatile("cp.async.commit_group;");

    const int warpM = (wid % 6) * 32;
    const int warpN = (wid / 6) * 64;
    const int aRow = warpM + (lid & 15);
    const int aK   = (lid >> 4) << 3;
    const int bN   = warpN + (lid & 7) + ((lid >> 4) << 3);
    const int bK   = ((lid >> 3) & 1) << 3;
    const int g    = lid >> 2;
    const int tg   = lid & 3;

    float acc[2][8][4];
#pragma unroll
    for (int i = 0; i < 2; i++)
#pragma unroll
        for (int j = 0; j < 8; j++)
#pragma unroll
            for (int c = 0; c < 4; c++) acc[i][j][c] = 0.0f;

    for (int chunk = 0; chunk < 18; chunk++) {
        __syncthreads();   // all warps done reading stage[(chunk-1)%3]
        if (chunk + 2 < 18) {
            prefetch_chunk(X16, XB, Wh, Wl, uS + ((chunk + 2) % 3) * STAGE,
                           chunk + 2, t, m0, M);
            asm volatile("cp.async.commit_group;");
        }
        if (chunk < 16)       asm volatile("cp.async.wait_group 2;");
        else if (chunk == 16) asm volatile("cp.async.wait_group 1;");
        else                  asm volatile("cp.async.wait_group 0;");
        __syncthreads();

        const uint32_t uA  = uS + (chunk % 3) * STAGE;
        const uint32_t uBh = uA + A_ST;
        const uint32_t uBl = uBh + 128 * CH * 2;

#pragma unroll
        for (int ks = 0; ks < 4; ks++) {
            const int kk = ks * 16;
            uint32_t a[2][4];
#pragma unroll
            for (int mi = 0; mi < 2; mi++) {
                const uint32_t ao = (uint32_t)(((aRow + mi * 16) * CH + (aK + kk)) * 2);
                LDSM_X4(a[mi][0], a[mi][1], a[mi][2], a[mi][3], uA + ao);
            }
            uint32_t bh[4][4], bl[4][4];
#pragma unroll
            for (int bq = 0; bq < 4; bq++) {
                const uint32_t bo = (uint32_t)(((bN + bq * 16) * CH + (bK + kk)) * 2);
                LDSM_X4(bh[bq][0], bh[bq][1], bh[bq][2], bh[bq][3], uBh + bo);
                LDSM_X4(bl[bq][0], bl[bq][1], bl[bq][2], bl[bq][3], uBl + bo);
            }
#pragma unroll
            for (int mi = 0; mi < 2; mi++)
#pragma unroll
                for (int nj = 0; nj < 8; nj++) {
                    const int bq = nj >> 1, hi = (nj & 1) << 1;
                    MMAF16(acc[mi][nj], a[mi], bh[bq][hi], bh[bq][hi + 1]);
                    MMAF16(acc[mi][nj], a[mi], bl[bq][hi], bl[bq][hi + 1]);
                }
        }
    }

    // Fused epilogue: layer1 -> relu + fp16 h16; layer2 -> fp32 out.
#pragma unroll
    for (int mi = 0; mi < 2; mi++) {
#pragma unroll
        for (int nj = 0; nj < 8; nj++) {
            const int col = warpN + nj * 8 + tg * 2;
            const float bx = bias[col], by = bias[col + 1];
            const int r0 = m0 + warpM + mi * 16 + g;
            const int r1 = r0 + 8;
            float2 v0 = make_float2(acc[mi][nj][0] + bx, acc[mi][nj][1] + by);
            float2 v1 = make_float2(acc[mi][nj][2] + bx, acc[mi][nj][3] + by);
            if (outH) {
                v0.x = fmaxf(v0.x, 0.f); v0.y = fmaxf(v0.y, 0.f);
                v1.x = fmaxf(v1.x, 0.f); v1.y = fmaxf(v1.y, 0.f);
                if (r0 < M)
                    *(__half2*)(outH + (size_t)r0 * DD + col) = __float22half2_rn(v0);
                if (r1 < M)
                    *(__half2*)(outH + (size_t)r1 * DD + col) = __float22half2_rn(v1);
            } else {
                if (r0 < M) *(float2*)(outF + (size_t)r0 * DD + col) = v0;
                if (r1 < M) *(float2*)(outF + (size_t)r1 * DD + col) = v1;
            }
        }
    }
}

// ---------------------------------------------------------------------------
// Launch
// ---------------------------------------------------------------------------
extern "C" void kernel_launch(void* const* d_in, const int* in_sizes, int n_in,
                              void* d_out, int out_size) {
    const float* x     = (const float*)d_in[0];
    const int*   ei    = (const int*)d_in[1];
    const int*   et    = (const int*)d_in[2];
    const float* W1    = (const float*)d_in[3];
    const float* root1 = (const float*)d_in[4];
    const float* b1    = (const float*)d_in[5];
    const float* W2    = (const float*)d_in[6];
    const float* root2 = (const float*)d_in[7];
    const float* b2    = (const float*)d_in[8];
    float* out = (float*)d_out;

    const int E = in_sizes[1] / 2;
    const int N = in_sizes[0] / DD;

    __half *x16, *h16, *xbar, *wh, *wl;
    int *cnt, *off, *cur, *bsum, *pack;
    cudaGetSymbolAddress((void**)&x16,  g_x16);
    cudaGetSymbolAddress((void**)&h16,  g_h16);
    cudaGetSymbolAddress((void**)&xbar, g_xbar);
    cudaGetSymbolAddress((void**)&wh,   g_wh);
    cudaGetSymbolAddress((void**)&wl,   g_wl);
    cudaGetSymbolAddress((void**)&cnt,  g_cnt);
    cudaGetSymbolAddress((void**)&off,  g_off);
    cudaGetSymbolAddress((void**)&cur,  g_cur);
    cudaGetSymbolAddress((void**)&bsum, g_bsum);
    cudaGetSymbolAddress((void**)&pack, g_pack);

    cudaFuncSetAttribute(gemmK_k, cudaFuncAttributeMaxDynamicSharedMemorySize, GSMEM);

    const int gemm_grid = (N + TM - 1) / TM;
    const int agg_grid  = (NN * 32 + 255) / 256;
    const int nb = (M8 + 1023) / 1024;
    const size_t n4 = (size_t)N * DD / 4;

    detect_k<<<1, 256>>>(et, E);
    zero_cnt_k<<<(M8 + 255) / 256, 256>>>(cnt);
    count_k<<<(E + 255) / 256, 256>>>(ei, et, cnt, E);
    scan1_k<<<nb, 256>>>(cnt, off, bsum, M8);
    scan2_k<<<1, 1024>>>(bsum, nb);
    scan3_k<<<(M8 + 255) / 256, 256>>>(off, cur, bsum, M8);
    scatter_k<<<(E + 255) / 256, 256>>>(ei, et, cur, pack, E);

    cvt16_k<<<(int)((n4 + 255) / 256), 256>>>(x, x16, n4);

    // Layer 1: h16 = relu( x@root1 + b1 + sum_r xbar_r@W1r )
    splitw9_k<<<(9 * DD * DD + 255) / 256, 256>>>(root1, W1, wh, wl);
    aggx_k<<<agg_grid, 256>>>(off, pack, x16, xbar, E);
    gemmK_k<<<gemm_grid, NTHR, GSMEM>>>(x16, xbar, wh, wl, b1, nullptr, h16, N);

    // Layer 2: out = h@root2 + b2 + sum_r hbar_r@W2r
    splitw9_k<<<(9 * DD * DD + 255) / 256, 256>>>(root2, W2, wh, wl);
    aggx_k<<<agg_grid, 256>>>(off, pack, h16, xbar, E);
    gemmK_k<<<gemm_grid, NTHR, GSMEM>>>(h16, xbar, wh, wl, b2, out, nullptr, N);
}

// round 11
// speedup vs baseline: 3.2345x; 1.2939x over previous
#include <cuda_runtime.h>
#include <cuda_fp16.h>
#include <cstdint>

#define NN 100000
#define EE 1600000
#define RR 8
#define DD 128
#define M8 (NN * RR)       // sort bins, key = dst*8 + rel

// ---------------------------------------------------------------------------
// Scratch (device globals; no allocation allowed anywhere).
// ---------------------------------------------------------------------------
__device__ __align__(16) __half g_x16[(size_t)NN * DD];        // fp16 features (layer in)
__device__ __align__(16) __half g_h16[(size_t)NN * DD];        // fp16 hidden
__device__ __align__(16) __half g_xbar[(size_t)NN * RR * DD];  // per-(dst,rel) means
__device__ __align__(16) __half g_w16[9 * DD * DD];  // [mat][n][k] weights fp16
__device__ int g_cnt[M8];
__device__ int g_off[M8];
__device__ int g_cur[M8];
__device__ int g_bsum[1024];
__device__ int g_pack[EE];     // src ids, sorted by (dst,rel)
__device__ int g_shift;        // 1 if edge arrays are int64, 0 if int32

// ---------------------------------------------------------------------------
// dtype autodetect (int64 edges => all odd 32-bit words zero)
// ---------------------------------------------------------------------------
__global__ void detect_k(const int* __restrict__ et, int E) {
    __shared__ int any;
    if (threadIdx.x == 0) any = 0;
    __syncthreads();
    int n = min(E, 4096);
    int local = 0;
    for (int i = threadIdx.x; i < n; i += blockDim.x) local |= et[2 * i + 1];
    if (local) atomicOr(&any, 1);
    __syncthreads();
    if (threadIdx.x == 0) g_shift = any ? 0 : 1;
}

// ---------------------------------------------------------------------------
// Counting sort by key (dst*8 + rel)
// ---------------------------------------------------------------------------
__global__ void zero_cnt_k(int* __restrict__ c) {
    int i = blockIdx.x * blockDim.x + threadIdx.x;
    if (i < M8) c[i] = 0;
}
__global__ void count_k(const int* __restrict__ ei, const int* __restrict__ et,
                        int* __restrict__ cnt, int E) {
    int e = blockIdx.x * blockDim.x + threadIdx.x;
    if (e < E) {
        const int sh = g_shift;
        int d = ei[(E << sh) + (e << sh)];
        int r = et[e << sh];
        if ((unsigned)d < NN && (unsigned)r < RR)
            atomicAdd(&cnt[d * RR + r], 1);
    }
}
__global__ void scan1_k(const int* __restrict__ cnt, int* __restrict__ off,
                        int* __restrict__ bsum, int M) {
    __shared__ int wsum[8];
    const int t = threadIdx.x;
    const int base = blockIdx.x * 1024 + t * 4;
    int v0 = 0, v1 = 0, v2 = 0, v3 = 0;
    if (base + 0 < M) v0 = cnt[base + 0];
    if (base + 1 < M) v1 = cnt[base + 1];
    if (base + 2 < M) v2 = cnt[base + 2];
    if (base + 3 < M) v3 = cnt[base + 3];
    const int tsum = v0 + v1 + v2 + v3;
    const int lane = t & 31, wid = t >> 5;
    int x = tsum;
#pragma unroll
    for (int o = 1; o < 32; o <<= 1) {
        int y = __shfl_up_sync(~0u, x, o);
        if (lane >= o) x += y;
    }
    if (lane == 31) wsum[wid] = x;
    __syncthreads();
    if (wid == 0) {
        int w = (lane < 8) ? wsum[lane] : 0;
#pragma unroll
        for (int o = 1; o < 8; o <<= 1) {
            int y = __shfl_up_sync(~0u, w, o);
            if (lane >= o) w += y;
        }
        if (lane < 8) wsum[lane] = w;
    }
    __syncthreads();
    const int excl = x - tsum + (wid > 0 ? wsum[wid - 1] : 0);
    if (base + 0 < M) off[base + 0] = excl;
    if (base + 1 < M) off[base + 1] = excl + v0;
    if (base + 2 < M) off[base + 2] = excl + v0 + v1;
    if (base + 3 < M) off[base + 3] = excl + v0 + v1 + v2;
    if (t == 0) bsum[blockIdx.x] = wsum[7];
}
__global__ void scan2_k(int* __restrict__ bsum, int nb) {
    __shared__ int sh[1024];
    const int t = threadIdx.x;
    sh[t] = (t < nb) ? bsum[t] : 0;
    __syncthreads();
    for (int o = 1; o < 1024; o <<= 1) {
        int v = (t >= o) ? sh[t - o] : 0;
        __syncthreads();
        sh[t] += v;
        __syncthreads();
    }
    if (t < nb) bsum[t] = (t == 0) ? 0 : sh[t - 1];
}
__global__ void scan3_k(int* __restrict__ off, int* __restrict__ cur,
                        const int* __restrict__ bsum, int M) {
    int i = blockIdx.x * blockDim.x + threadIdx.x;
    if (i < M) {
        int v = off[i] + bsum[i >> 10];
        off[i] = v;
        cur[i] = v;
    }
}
__global__ void scatter_k(const int* __restrict__ ei, const int* __restrict__ et,
                          int* __restrict__ cur, int* __restrict__ pack, int E) {
    int e = blockIdx.x * blockDim.x + threadIdx.x;
    if (e < E) {
        const int sh = g_shift;
        int s = ei[e << sh];
        int d = ei[(E << sh) + (e << sh)];
        int r = et[e << sh];
        if ((unsigned)d < NN && (unsigned)r < RR && (unsigned)s < NN) {
            int pos = atomicAdd(&cur[d * RR + r], 1);
            pack[pos] = s;
        }
    }
}

// ---------------------------------------------------------------------------
// fp32 -> fp16 feature conversion
// ---------------------------------------------------------------------------
__global__ void cvt16_k(const float* __restrict__ A, __half* __restrict__ B, size_t n4) {
    size_t i = (size_t)blockIdx.x * blockDim.x + threadIdx.x;
    if (i < n4) {
        float4 v = ((const float4*)A)[i];
        __half2 a = __float22half2_rn(make_float2(v.x, v.y));
        __half2 b = __float22half2_rn(make_float2(v.z, v.w));
        ((__half2*)B)[2 * i]     = a;
        ((__half2*)B)[2 * i + 1] = b;
    }
}

// ---------------------------------------------------------------------------
// Weight transpose to fp16: out[mat][n][k]; mat0=root, 1..8=W[r]
// ---------------------------------------------------------------------------
__global__ void cvtw9_k(const float* __restrict__ root, const float* __restrict__ W,
                        __half* __restrict__ H) {
    int idx = blockIdx.x * blockDim.x + threadIdx.x;
    if (idx < 9 * DD * DD) {
        int mat = idx >> 14;
        int rem = idx & 16383;
        int n = rem >> 7;
        int k = rem & 127;
        float v = (mat == 0) ? root[(k << 7) + n] : W[((mat - 1) << 14) + (k << 7) + n];
        H[idx] = __float2half_rn(v);
    }
}

// ---------------------------------------------------------------------------
// Gather-mean: xbar[d][r] = mean over edges (sorted (dst,rel)) of src16[src].
// One warp per dst; gathers hit the 25.6MB L2-resident fp16 feature buffer.
// ---------------------------------------------------------------------------
__global__ void aggx_k(const int* __restrict__ off, const int* __restrict__ pack,
                       const __half* __restrict__ src16, __half* __restrict__ xbar,
                       int E) {
    const int d = (blockIdx.x * blockDim.x + threadIdx.x) >> 5;
    if (d >= NN) return;
    const int lane = threadIdx.x & 31;
    const int base = d * RR;

    int v = E;
    if (lane < 9 && base + lane < M8) v = off[base + lane];

    const int c4 = lane * 4;
#pragma unroll
    for (int r = 0; r < RR; r++) {
        const int lo = __shfl_sync(~0u, v, r);
        const int hi = __shfl_sync(~0u, v, r + 1);
        float4 acc = make_float4(0.f, 0.f, 0.f, 0.f);
        int i = lo;
        for (; i + 2 <= hi; i += 2) {
            const int s0 = pack[i], s1 = pack[i + 1];
            const float2 q0 = *(const float2*)(src16 + (size_t)s0 * DD + c4);
            const float2 q1 = *(const float2*)(src16 + (size_t)s1 * DD + c4);
            const __half2 a0 = *(const __half2*)&q0.x, b0 = *(const __half2*)&q0.y;
            const __half2 a1 = *(const __half2*)&q1.x, b1 = *(const __half2*)&q1.y;
            float2 f;
            f = __half22float2(a0); acc.x += f.x; acc.y += f.y;
            f = __half22float2(b0); acc.z += f.x; acc.w += f.y;
            f = __half22float2(a1); acc.x += f.x; acc.y += f.y;
            f = __half22float2(b1); acc.z += f.x; acc.w += f.y;
        }
        for (; i < hi; i++) {
            const int s = pack[i];
            const float2 q = *(const float2*)(src16 + (size_t)s * DD + c4);
            const __half2 a = *(const __half2*)&q.x, b = *(const __half2*)&q.y;
            float2 f;
            f = __half22float2(a); acc.x += f.x; acc.y += f.y;
            f = __half22float2(b); acc.z += f.x; acc.w += f.y;
        }
        const float inv = (hi > lo) ? (1.0f / (float)(hi - lo)) : 0.f;
        __half2 o0 = __float22half2_rn(make_float2(acc.x * inv, acc.y * inv));
        __half2 o1 = __float22half2_rn(make_float2(acc.z * inv, acc.w * inv));
        float2 ov;
        *(__half2*)&ov.x = o0;
        *(__half2*)&ov.y = o1;
        *(float2*)(xbar + ((size_t)base + r) * DD + c4) = ov;
    }
}

// ---------------------------------------------------------------------------
// K=1152 GEMM: out = act( concat(x16, xbar_0..7)[M,1152] @ Wcat[1152,128] + b )
// 384 threads, tile M=192 x N=128. 18 k-half chunks (9 mats x 2 halves of 64)
// through a 3-stage cp.async ring (A fp16 + B fp16 per stage).
// Single fp16 MMA pass; fp32 accumulate; fused bias/relu epilogue.
// ---------------------------------------------------------------------------
#define TM 192
#define NTHR 384
#define CH 72                            // chunk row stride (64 data + 8 pad)
#define A_ST (TM * CH * 2)               // 27648
#define B_ST (128 * CH * 2)              // 18432
#define STAGE (A_ST + B_ST)              // 46080
#define GSMEM (3 * STAGE)                // 138240

static __device__ __forceinline__ uint32_t smem_u32(const void* p) {
    uint32_t a;
    asm("{ .reg .u64 t; cvta.to.shared.u64 t, %1; cvt.u32.u64 %0, t; }"
        : "=r"(a) : "l"(p));
    return a;
}
#define LDSM_X4(r0, r1, r2, r3, addr) \
    asm volatile("ldmatrix.sync.aligned.m8n8.x4.shared.b16 {%0,%1,%2,%3}, [%4];" \
                 : "=r"(r0), "=r"(r1), "=r"(r2), "=r"(r3) : "r"(addr))
#define MMAF16(d, a, b0, b1) \
    asm volatile("mma.sync.aligned.m16n8k16.row.col.f32.f16.f16.f32 " \
                 "{%0,%1,%2,%3}, {%4,%5,%6,%7}, {%8,%9}, {%0,%1,%2,%3};" \
                 : "+f"((d)[0]), "+f"((d)[1]), "+f"((d)[2]), "+f"((d)[3]) \
                 : "r"((a)[0]), "r"((a)[1]), "r"((a)[2]), "r"((a)[3]), \
                   "r"(b0), "r"(b1))
#define CP_ASYNC16Z(saddr, gptr, sz) \
    asm volatile("cp.async.cg.shared.global [%0], [%1], 16, %2;" \
                 :: "r"(saddr), "l"(gptr), "r"(sz))
#define CP_ASYNC16(saddr, gptr) \
    asm volatile("cp.async.cg.shared.global [%0], [%1], 16;" \
                 :: "r"(saddr), "l"(gptr))

static __device__ __forceinline__ void prefetch_chunk(
    const __half* __restrict__ X16, const __half* __restrict__ XB,
    const __half* __restrict__ W16,
    uint32_t uStage, int chunk, int t, int m0, int M) {
    const int mat = chunk >> 1;
    const int k0  = (chunk & 1) << 6;
    // --- A: 192 rows x 64 halves = 8 x 16B per row -> 1536 ops, 4 iters ---
    const uint32_t uA = uStage;
#pragma unroll
    for (int it = 0; it < 4; it++) {
        const int idx = it * NTHR + t;
        const int row = idx >> 3;
        const int c16 = (idx & 7) * 8;
        const int gr  = m0 + row;
        const int ok  = (gr < M);
        const int grc = ok ? gr : (M - 1);
        const __half* ap = (mat == 0)
            ? X16 + (size_t)grc * DD + k0 + c16
            : XB  + ((size_t)grc * RR + (mat - 1)) * DD + k0 + c16;
        CP_ASYNC16Z(uA + (uint32_t)(row * CH + c16) * 2, ap, ok ? 16 : 0);
    }
    // --- B: 128 rows x 64 halves -> 1024 ops, 3 iters ---
    const __half* bp = W16 + (size_t)mat * DD * DD + k0;
    const uint32_t uB = uStage + A_ST;
#pragma unroll
    for (int it = 0; it < 3; it++) {
        const int idx = it * NTHR + t;
        if (idx < 1024) {
            const int row = idx >> 3;
            const int c16 = (idx & 7) * 8;
            CP_ASYNC16(uB + (uint32_t)(row * CH + c16) * 2, bp + row * DD + c16);
        }
    }
}

__global__ void __launch_bounds__(NTHR, 1)
gemmK_k(const __half* __restrict__ X16, const __half* __restrict__ XB,
        const __half* __restrict__ W16,
        const float* __restrict__ bias, float* __restrict__ outF,
        __half* __restrict__ outH, int M) {
    extern __shared__ char smc[];
    const uint32_t uS = smem_u32(smc);

    const int t   = threadIdx.x;
    const int wid = t >> 5, lid = t & 31;
    const int m0  = blockIdx.x * TM;

    prefetch_chunk(X16, XB, W16, uS + 0 * STAGE, 0, t, m0, M);
    asm volatile("cp.async.commit_group;");
    prefetch_chunk(X16, XB, W16, uS + 1 * STAGE, 1, t, m0, M);
    asm volatile("cp.async.commit_group;");

    const int warpM = (wid % 6) * 32;
    const int warpN = (wid / 6) * 64;
    const int aRow = warpM + (lid & 15);
    const int aK   = (lid >> 4) << 3;
    const int bN   = warpN + (lid & 7) + ((lid >> 4) << 3);
    const int bK   = ((lid >> 3) & 1) << 3;
    const int g    = lid >> 2;
    const int tg   = lid & 3;

    float acc[2][8][4];
#pragma unroll
    for (int i = 0; i < 2; i++)
#pragma unroll
        for (int j = 0; j < 8; j++)
#pragma unroll
            for (int c = 0; c < 4; c++) acc[i][j][c] = 0.0f;

    for (int chunk = 0; chunk < 18; chunk++) {
        __syncthreads();   // all warps done reading stage[(chunk-1)%3]
        if (chunk + 2 < 18) {
            prefetch_chunk(X16, XB, W16, uS + ((chunk + 2) % 3) * STAGE,
                           chunk + 2, t, m0, M);
            asm volatile("cp.async.commit_group;");
        }
        if (chunk < 16)       asm volatile("cp.async.wait_group 2;");
        else if (chunk == 16) asm volatile("cp.async.wait_group 1;");
        else                  asm volatile("cp.async.wait_group 0;");
        __syncthreads();

        const uint32_t uA = uS + (chunk % 3) * STAGE;
        const uint32_t uB = uA + A_ST;

#pragma unroll
        for (int ks = 0; ks < 4; ks++) {
            const int kk = ks * 16;
            uint32_t a[2][4];
#pragma unroll
            for (int mi = 0; mi < 2; mi++) {
                const uint32_t ao = (uint32_t)(((aRow + mi * 16) * CH + (aK + kk)) * 2);
                LDSM_X4(a[mi][0], a[mi][1], a[mi][2], a[mi][3], uA + ao);
            }
            uint32_t b[4][4];
#pragma unroll
            for (int bq = 0; bq < 4; bq++) {
                const uint32_t bo = (uint32_t)(((bN + bq * 16) * CH + (bK + kk)) * 2);
                LDSM_X4(b[bq][0], b[bq][1], b[bq][2], b[bq][3], uB + bo);
            }
#pragma unroll
            for (int mi = 0; mi < 2; mi++)
#pragma unroll
                for (int nj = 0; nj < 8; nj++) {
                    const int bq = nj >> 1, hi = (nj & 1) << 1;
                    MMAF16(acc[mi][nj], a[mi], b[bq][hi], b[bq][hi + 1]);
                }
        }
    }

    // Fused epilogue: layer1 -> relu + fp16 h16; layer2 -> fp32 out.
#pragma unroll
    for (int mi = 0; mi < 2; mi++) {
#pragma unroll
        for (int nj = 0; nj < 8; nj++) {
            const int col = warpN + nj * 8 + tg * 2;
            const float bx = bias[col], by = bias[col + 1];
            const int r0 = m0 + warpM + mi * 16 + g;
            const int r1 = r0 + 8;
            float2 v0 = make_float2(acc[mi][nj][0] + bx, acc[mi][nj][1] + by);
            float2 v1 = make_float2(acc[mi][nj][2] + bx, acc[mi][nj][3] + by);
            if (outH) {
                v0.x = fmaxf(v0.x, 0.f); v0.y = fmaxf(v0.y, 0.f);
                v1.x = fmaxf(v1.x, 0.f); v1.y = fmaxf(v1.y, 0.f);
                if (r0 < M)
                    *(__half2*)(outH + (size_t)r0 * DD + col) = __float22half2_rn(v0);
                if (r1 < M)
                    *(__half2*)(outH + (size_t)r1 * DD + col) = __float22half2_rn(v1);
            } else {
                if (r0 < M) *(float2*)(outF + (size_t)r0 * DD + col) = v0;
                if (r1 < M) *(float2*)(outF + (size_t)r1 * DD + col) = v1;
            }
        }
    }
}

// ---------------------------------------------------------------------------
// Launch
// ---------------------------------------------------------------------------
extern "C" void kernel_launch(void* const* d_in, const int* in_sizes, int n_in,
                              void* d_out, int out_size) {
    const float* x     = (const float*)d_in[0];
    const int*   ei    = (const int*)d_in[1];
    const int*   et    = (const int*)d_in[2];
    const float* W1    = (const float*)d_in[3];
    const float* root1 = (const float*)d_in[4];
    const float* b1    = (const float*)d_in[5];
    const float* W2    = (const float*)d_in[6];
    const float* root2 = (const float*)d_in[7];
    const float* b2    = (const float*)d_in[8];
    float* out = (float*)d_out;

    const int E = in_sizes[1] / 2;
    const int N = in_sizes[0] / DD;

    __half *x16, *h16, *xbar, *w16;
    int *cnt, *off, *cur, *bsum, *pack;
    cudaGetSymbolAddress((void**)&x16,  g_x16);
    cudaGetSymbolAddress((void**)&h16,  g_h16);
    cudaGetSymbolAddress((void**)&xbar, g_xbar);
    cudaGetSymbolAddress((void**)&w16,  g_w16);
    cudaGetSymbolAddress((void**)&cnt,  g_cnt);
    cudaGetSymbolAddress((void**)&off,  g_off);
    cudaGetSymbolAddress((void**)&cur,  g_cur);
    cudaGetSymbolAddress((void**)&bsum, g_bsum);
    cudaGetSymbolAddress((void**)&pack, g_pack);

    cudaFuncSetAttribute(gemmK_k, cudaFuncAttributeMaxDynamicSharedMemorySize, GSMEM);

    const int gemm_grid = (N + TM - 1) / TM;
    const int agg_grid  = (NN * 32 + 255) / 256;
    const int nb = (M8 + 1023) / 1024;
    const size_t n4 = (size_t)N * DD / 4;

    detect_k<<<1, 256>>>(et, E);
    zero_cnt_k<<<(M8 + 255) / 256, 256>>>(cnt);
    count_k<<<(E + 255) / 256, 256>>>(ei, et, cnt, E);
    scan1_k<<<nb, 256>>>(cnt, off, bsum, M8);
    scan2_k<<<1, 1024>>>(bsum, nb);
    scan3_k<<<(M8 + 255) / 256, 256>>>(off, cur, bsum, M8);
    scatter_k<<<(E + 255) / 256, 256>>>(ei, et, cur, pack, E);

    cvt16_k<<<(int)((n4 + 255) / 256), 256>>>(x, x16, n4);

    // Layer 1: h16 = relu( x@root1 + b1 + sum_r xbar_r@W1r )
    cvtw9_k<<<(9 * DD * DD + 255) / 256, 256>>>(root1, W1, w16);
    aggx_k<<<agg_grid, 256>>>(off, pack, x16, xbar, E);
    gemmK_k<<<gemm_grid, NTHR, GSMEM>>>(x16, xbar, w16, b1, nullptr, h16, N);

    // Layer 2: out = h@root2 + b2 + sum_r hbar_r@W2r
    cvtw9_k<<<(9 * DD * DD + 255) / 256, 256>>>(root2, W2, w16);
    aggx_k<<<agg_grid, 256>>>(off, pack, h16, xbar, E);
    gemmK_k<<<gemm_grid, NTHR, GSMEM>>>(h16, xbar, w16, b2, out, nullptr, N);
}

// round 12
// speedup vs baseline: 3.5980x; 1.1124x over previous
#include <cuda_runtime.h>
#include <cuda_fp16.h>
#include <cstdint>

#define NN 100000
#define EE 1600000
#define RR 8
#define DD 128
#define M8 (NN * RR)       // sort bins, key = dst*8 + rel

// ---------------------------------------------------------------------------
// Scratch (device globals; no allocation allowed anywhere).
// ---------------------------------------------------------------------------
__device__ __align__(16) __half g_x16[(size_t)NN * DD];        // fp16 features (layer in)
__device__ __align__(16) __half g_h16[(size_t)NN * DD];        // fp16 hidden
__device__ __align__(16) __half g_xbar[(size_t)NN * RR * DD];  // per-(dst,rel) means
__device__ __align__(16) __half g_w16[9 * DD * DD];  // [mat][n][k] weights fp16
__device__ int g_cnt[M8];
__device__ int g_off[M8];
__device__ int g_cur[M8];
__device__ int g_bsum[1024];
__device__ int g_pack[EE];     // src ids, sorted by (dst,rel)
__device__ int g_shift;        // 1 if edge arrays are int64, 0 if int32

// ---------------------------------------------------------------------------
// dtype autodetect (int64 edges => all odd 32-bit words zero)
// ---------------------------------------------------------------------------
__global__ void detect_k(const int* __restrict__ et, int E) {
    __shared__ int any;
    if (threadIdx.x == 0) any = 0;
    __syncthreads();
    int n = min(E, 4096);
    int local = 0;
    for (int i = threadIdx.x; i < n; i += blockDim.x) local |= et[2 * i + 1];
    if (local) atomicOr(&any, 1);
    __syncthreads();
    if (threadIdx.x == 0) g_shift = any ? 0 : 1;
}

// ---------------------------------------------------------------------------
// Counting sort by key (dst*8 + rel)
// ---------------------------------------------------------------------------
__global__ void zero_cnt_k(int* __restrict__ c) {
    int i = blockIdx.x * blockDim.x + threadIdx.x;
    if (i < M8) c[i] = 0;
}
__global__ void count_k(const int* __restrict__ ei, const int* __restrict__ et,
                        int* __restrict__ cnt, int E) {
    int e = blockIdx.x * blockDim.x + threadIdx.x;
    if (e < E) {
        const int sh = g_shift;
        int d = ei[(E << sh) + (e << sh)];
        int r = et[e << sh];
        if ((unsigned)d < NN && (unsigned)r < RR)
            atomicAdd(&cnt[d * RR + r], 1);
    }
}
__global__ void scan1_k(const int* __restrict__ cnt, int* __restrict__ off,
                        int* __restrict__ bsum, int M) {
    __shared__ int wsum[8];
    const int t = threadIdx.x;
    const int base = blockIdx.x * 1024 + t * 4;
    int v0 = 0, v1 = 0, v2 = 0, v3 = 0;
    if (base + 0 < M) v0 = cnt[base + 0];
    if (base + 1 < M) v1 = cnt[base + 1];
    if (base + 2 < M) v2 = cnt[base + 2];
    if (base + 3 < M) v3 = cnt[base + 3];
    const int tsum = v0 + v1 + v2 + v3;
    const int lane = t & 31, wid = t >> 5;
    int x = tsum;
#pragma unroll
    for (int o = 1; o < 32; o <<= 1) {
        int y = __shfl_up_sync(~0u, x, o);
        if (lane >= o) x += y;
    }
    if (lane == 31) wsum[wid] = x;
    __syncthreads();
    if (wid == 0) {
        int w = (lane < 8) ? wsum[lane] : 0;
#pragma unroll
        for (int o = 1; o < 8; o <<= 1) {
            int y = __shfl_up_sync(~0u, w, o);
            if (lane >= o) w += y;
        }
        if (lane < 8) wsum[lane] = w;
    }
    __syncthreads();
    const int excl = x - tsum + (wid > 0 ? wsum[wid - 1] : 0);
    if (base + 0 < M) off[base + 0] = excl;
    if (base + 1 < M) off[base + 1] = excl + v0;
    if (base + 2 < M) off[base + 2] = excl + v0 + v1;
    if (base + 3 < M) off[base + 3] = excl + v0 + v1 + v2;
    if (t == 0) bsum[blockIdx.x] = wsum[7];
}
__global__ void scan2_k(int* __restrict__ bsum, int nb) {
    __shared__ int sh[1024];
    const int t = threadIdx.x;
    sh[t] = (t < nb) ? bsum[t] : 0;
    __syncthreads();
    for (int o = 1; o < 1024; o <<= 1) {
        int v = (t >= o) ? sh[t - o] : 0;
        __syncthreads();
        sh[t] += v;
        __syncthreads();
    }
    if (t < nb) bsum[t] = (t == 0) ? 0 : sh[t - 1];
}
__global__ void scan3_k(int* __restrict__ off, int* __restrict__ cur,
                        const int* __restrict__ bsum, int M) {
    int i = blockIdx.x * blockDim.x + threadIdx.x;
    if (i < M) {
        int v = off[i] + bsum[i >> 10];
        off[i] = v;
        cur[i] = v;
    }
}
__global__ void scatter_k(const int* __restrict__ ei, const int* __restrict__ et,
                          int* __restrict__ cur, int* __restrict__ pack, int E) {
    int e = blockIdx.x * blockDim.x + threadIdx.x;
    if (e < E) {
        const int sh = g_shift;
        int s = ei[e << sh];
        int d = ei[(E << sh) + (e << sh)];
        int r = et[e << sh];
        if ((unsigned)d < NN && (unsigned)r < RR && (unsigned)s < NN) {
            int pos = atomicAdd(&cur[d * RR + r], 1);
            pack[pos] = s;
        }
    }
}

// ---------------------------------------------------------------------------
// fp32 -> fp16 feature conversion
// ---------------------------------------------------------------------------
__global__ void cvt16_k(const float* __restrict__ A, __half* __restrict__ B, size_t n4) {
    size_t i = (size_t)blockIdx.x * blockDim.x + threadIdx.x;
    if (i < n4) {
        float4 v = ((const float4*)A)[i];
        __half2 a = __float22half2_rn(make_float2(v.x, v.y));
        __half2 b = __float22half2_rn(make_float2(v.z, v.w));
        ((__half2*)B)[2 * i]     = a;
        ((__half2*)B)[2 * i + 1] = b;
    }
}

// ---------------------------------------------------------------------------
// Weight transpose to fp16: out[mat][n][k]; mat0=root, 1..8=W[r]
// ---------------------------------------------------------------------------
__global__ void cvtw9_k(const float* __restrict__ root, const float* __restrict__ W,
                        __half* __restrict__ H) {
    int idx = blockIdx.x * blockDim.x + threadIdx.x;
    if (idx < 9 * DD * DD) {
        int mat = idx >> 14;
        int rem = idx & 16383;
        int n = rem >> 7;
        int k = rem & 127;
        float v = (mat == 0) ? root[(k << 7) + n] : W[((mat - 1) << 14) + (k << 7) + n];
        H[idx] = __float2half_rn(v);
    }
}

// ---------------------------------------------------------------------------
// Gather-mean: xbar[d][r] = mean over edges (sorted (dst,rel)) of src16[src].
// One warp per dst; gathers hit the 25.6MB L2-resident fp16 feature buffer.
// 4-way unrolled gather for MLP.
// ---------------------------------------------------------------------------
__global__ void aggx_k(const int* __restrict__ off, const int* __restrict__ pack,
                       const __half* __restrict__ src16, __half* __restrict__ xbar,
                       int E) {
    const int d = (blockIdx.x * blockDim.x + threadIdx.x) >> 5;
    if (d >= NN) return;
    const int lane = threadIdx.x & 31;
    const int base = d * RR;

    int v = E;
    if (lane < 9 && base + lane < M8) v = off[base + lane];

    const int c4 = lane * 4;
#pragma unroll
    for (int r = 0; r < RR; r++) {
        const int lo = __shfl_sync(~0u, v, r);
        const int hi = __shfl_sync(~0u, v, r + 1);
        float4 acc = make_float4(0.f, 0.f, 0.f, 0.f);
        int i = lo;
        for (; i + 4 <= hi; i += 4) {
            const int s0 = pack[i],     s1 = pack[i + 1];
            const int s2 = pack[i + 2], s3 = pack[i + 3];
            const float2 q0 = *(const float2*)(src16 + (size_t)s0 * DD + c4);
            const float2 q1 = *(const float2*)(src16 + (size_t)s1 * DD + c4);
            const float2 q2 = *(const float2*)(src16 + (size_t)s2 * DD + c4);
            const float2 q3 = *(const float2*)(src16 + (size_t)s3 * DD + c4);
            float2 f;
            f = __half22float2(*(const __half2*)&q0.x); acc.x += f.x; acc.y += f.y;
            f = __half22float2(*(const __half2*)&q0.y); acc.z += f.x; acc.w += f.y;
            f = __half22float2(*(const __half2*)&q1.x); acc.x += f.x; acc.y += f.y;
            f = __half22float2(*(const __half2*)&q1.y); acc.z += f.x; acc.w += f.y;
            f = __half22float2(*(const __half2*)&q2.x); acc.x += f.x; acc.y += f.y;
            f = __half22float2(*(const __half2*)&q2.y); acc.z += f.x; acc.w += f.y;
            f = __half22float2(*(const __half2*)&q3.x); acc.x += f.x; acc.y += f.y;
            f = __half22float2(*(const __half2*)&q3.y); acc.z += f.x; acc.w += f.y;
        }
        for (; i < hi; i++) {
            const int s = pack[i];
            const float2 q = *(const float2*)(src16 + (size_t)s * DD + c4);
            float2 f;
            f = __half22float2(*(const __half2*)&q.x); acc.x += f.x; acc.y += f.y;
            f = __half22float2(*(const __half2*)&q.y); acc.z += f.x; acc.w += f.y;
        }
        const float inv = (hi > lo) ? (1.0f / (float)(hi - lo)) : 0.f;
        __half2 o0 = __float22half2_rn(make_float2(acc.x * inv, acc.y * inv));
        __half2 o1 = __float22half2_rn(make_float2(acc.z * inv, acc.w * inv));
        float2 ov;
        *(__half2*)&ov.x = o0;
        *(__half2*)&ov.y = o1;
        *(float2*)(xbar + ((size_t)base + r) * DD + c4) = ov;
    }
}

// ---------------------------------------------------------------------------
// K=1152 GEMM: out = act( concat(x16, xbar_0..7)[M,1152] @ Wcat[1152,128] + b )
// 256 threads (8 warps, 4m x 2n), tile M=128 x N=128, 2 CTAs/SM.
// 18 k-half chunks (9 mats x 2 halves of 64) through a 3-stage cp.async ring.
// Single fp16 MMA pass; fp32 accumulate; fused bias/relu epilogue.
// ---------------------------------------------------------------------------
#define TM 128
#define NTHR 256
#define CH 72                            // chunk row stride (64 data + 8 pad)
#define A_ST (TM * CH * 2)               // 18432
#define B_ST (128 * CH * 2)              // 18432
#define STAGE (A_ST + B_ST)              // 36864
#define GSMEM (3 * STAGE)                // 110592  (x2 CTAs = 221KB/SM)

static __device__ __forceinline__ uint32_t smem_u32(const void* p) {
    uint32_t a;
    asm("{ .reg .u64 t; cvta.to.shared.u64 t, %1; cvt.u32.u64 %0, t; }"
        : "=r"(a) : "l"(p));
    return a;
}
#define LDSM_X4(r0, r1, r2, r3, addr) \
    asm volatile("ldmatrix.sync.aligned.m8n8.x4.shared.b16 {%0,%1,%2,%3}, [%4];" \
                 : "=r"(r0), "=r"(r1), "=r"(r2), "=r"(r3) : "r"(addr))
#define MMAF16(d, a, b0, b1) \
    asm volatile("mma.sync.aligned.m16n8k16.row.col.f32.f16.f16.f32 " \
                 "{%0,%1,%2,%3}, {%4,%5,%6,%7}, {%8,%9}, {%0,%1,%2,%3};" \
                 : "+f"((d)[0]), "+f"((d)[1]), "+f"((d)[2]), "+f"((d)[3]) \
                 : "r"((a)[0]), "r"((a)[1]), "r"((a)[2]), "r"((a)[3]), \
                   "r"(b0), "r"(b1))
#define CP_ASYNC16Z(saddr, gptr, sz) \
    asm volatile("cp.async.cg.shared.global [%0], [%1], 16, %2;" \
                 :: "r"(saddr), "l"(gptr), "r"(sz))
#define CP_ASYNC16(saddr, gptr) \
    asm volatile("cp.async.cg.shared.global [%0], [%1], 16;" \
                 :: "r"(saddr), "l"(gptr))

static __device__ __forceinline__ void prefetch_chunk(
    const __half* __restrict__ X16, const __half* __restrict__ XB,
    const __half* __restrict__ W16,
    uint32_t uStage, int chunk, int t, int m0, int M) {
    const int mat = chunk >> 1;
    const int k0  = (chunk & 1) << 6;
    // --- A: 128 rows x 64 halves = 8 x 16B per row -> 1024 ops, 4 iters ---
    const uint32_t uA = uStage;
#pragma unroll
    for (int it = 0; it < 4; it++) {
        const int idx = it * NTHR + t;
        const int row = idx >> 3;
        const int c16 = (idx & 7) * 8;
        const int gr  = m0 + row;
        const int ok  = (gr < M);
        const int grc = ok ? gr : (M - 1);
        const __half* ap = (mat == 0)
            ? X16 + (size_t)grc * DD + k0 + c16
            : XB  + ((size_t)grc * RR + (mat - 1)) * DD + k0 + c16;
        CP_ASYNC16Z(uA + (uint32_t)(row * CH + c16) * 2, ap, ok ? 16 : 0);
    }
    // --- B: 128 rows x 64 halves -> 1024 ops, 4 iters ---
    const __half* bp = W16 + (size_t)mat * DD * DD + k0;
    const uint32_t uB = uStage + A_ST;
#pragma unroll
    for (int it = 0; it < 4; it++) {
        const int idx = it * NTHR + t;
        const int row = idx >> 3;
        const int c16 = (idx & 7) * 8;
        CP_ASYNC16(uB + (uint32_t)(row * CH + c16) * 2, bp + row * DD + c16);
    }
}

__global__ void __launch_bounds__(NTHR, 2)
gemmK_k(const __half* __restrict__ X16, const __half* __restrict__ XB,
        const __half* __restrict__ W16,
        const float* __restrict__ bias, float* __restrict__ outF,
        __half* __restrict__ outH, int M) {
    extern __shared__ char smc[];
    const uint32_t uS = smem_u32(smc);

    const int t   = threadIdx.x;
    const int wid = t >> 5, lid = t & 31;
    const int m0  = blockIdx.x * TM;

    prefetch_chunk(X16, XB, W16, uS + 0 * STAGE, 0, t, m0, M);
    asm volatile("cp.async.commit_group;");
    prefetch_chunk(X16, XB, W16, uS + 1 * STAGE, 1, t, m0, M);
    asm volatile("cp.async.commit_group;");

    const int warpM = (wid & 3) * 32;
    const int warpN = (wid >> 2) * 64;
    const int aRow = warpM + (lid & 15);
    const int aK   = (lid >> 4) << 3;
    const int bN   = warpN + (lid & 7) + ((lid >> 4) << 3);
    const int bK   = ((lid >> 3) & 1) << 3;
    const int g    = lid >> 2;
    const int tg   = lid & 3;

    float acc[2][8][4];
#pragma unroll
    for (int i = 0; i < 2; i++)
#pragma unroll
        for (int j = 0; j < 8; j++)
#pragma unroll
            for (int c = 0; c < 4; c++) acc[i][j][c] = 0.0f;

    for (int chunk = 0; chunk < 18; chunk++) {
        __syncthreads();   // all warps done reading stage[(chunk-1)%3]
        if (chunk + 2 < 18) {
            prefetch_chunk(X16, XB, W16, uS + ((chunk + 2) % 3) * STAGE,
                           chunk + 2, t, m0, M);
            asm volatile("cp.async.commit_group;");
        }
        if (chunk < 16)       asm volatile("cp.async.wait_group 2;");
        else if (chunk == 16) asm volatile("cp.async.wait_group 1;");
        else                  asm volatile("cp.async.wait_group 0;");
        __syncthreads();

        const uint32_t uA = uS + (chunk % 3) * STAGE;
        const uint32_t uB = uA + A_ST;

#pragma unroll
        for (int ks = 0; ks < 4; ks++) {
            const int kk = ks * 16;
            uint32_t a[2][4];
#pragma unroll
            for (int mi = 0; mi < 2; mi++) {
                const uint32_t ao = (uint32_t)(((aRow + mi * 16) * CH + (aK + kk)) * 2);
                LDSM_X4(a[mi][0], a[mi][1], a[mi][2], a[mi][3], uA + ao);
            }
            uint32_t b[4][4];
#pragma unroll
            for (int bq = 0; bq < 4; bq++) {
                const uint32_t bo = (uint32_t)(((bN + bq * 16) * CH + (bK + kk)) * 2);
                LDSM_X4(b[bq][0], b[bq][1], b[bq][2], b[bq][3], uB + bo);
            }
#pragma unroll
            for (int mi = 0; mi < 2; mi++)
#pragma unroll
                for (int nj = 0; nj < 8; nj++) {
                    const int bq = nj >> 1, hi = (nj & 1) << 1;
                    MMAF16(acc[mi][nj], a[mi], b[bq][hi], b[bq][hi + 1]);
                }
        }
    }

    // Fused epilogue: layer1 -> relu + fp16 h16; layer2 -> fp32 out.
#pragma unroll
    for (int mi = 0; mi < 2; mi++) {
#pragma unroll
        for (int nj = 0; nj < 8; nj++) {
            const int col = warpN + nj * 8 + tg * 2;
            const float bx = bias[col], by = bias[col + 1];
            const int r0 = m0 + warpM + mi * 16 + g;
            const int r1 = r0 + 8;
            float2 v0 = make_float2(acc[mi][nj][0] + bx, acc[mi][nj][1] + by);
            float2 v1 = make_float2(acc[mi][nj][2] + bx, acc[mi][nj][3] + by);
            if (outH) {
                v0.x = fmaxf(v0.x, 0.f); v0.y = fmaxf(v0.y, 0.f);
                v1.x = fmaxf(v1.x, 0.f); v1.y = fmaxf(v1.y, 0.f);
                if (r0 < M)
                    *(__half2*)(outH + (size_t)r0 * DD + col) = __float22half2_rn(v0);
                if (r1 < M)
                    *(__half2*)(outH + (size_t)r1 * DD + col) = __float22half2_rn(v1);
            } else {
                if (r0 < M) *(float2*)(outF + (size_t)r0 * DD + col) = v0;
                if (r1 < M) *(float2*)(outF + (size_t)r1 * DD + col) = v1;
            }
        }
    }
}

// ---------------------------------------------------------------------------
// Launch
// ---------------------------------------------------------------------------
extern "C" void kernel_launch(void* const* d_in, const int* in_sizes, int n_in,
                              void* d_out, int out_size) {
    const float* x     = (const float*)d_in[0];
    const int*   ei    = (const int*)d_in[1];
    const int*   et    = (const int*)d_in[2];
    const float* W1    = (const float*)d_in[3];
    const float* root1 = (const float*)d_in[4];
    const float* b1    = (const float*)d_in[5];
    const float* W2    = (const float*)d_in[6];
    const float* root2 = (const float*)d_in[7];
    const float* b2    = (const float*)d_in[8];
    float* out = (float*)d_out;

    const int E = in_sizes[1] / 2;
    const int N = in_sizes[0] / DD;

    __half *x16, *h16, *xbar, *w16;
    int *cnt, *off, *cur, *bsum, *pack;
    cudaGetSymbolAddress((void**)&x16,  g_x16);
    cudaGetSymbolAddress((void**)&h16,  g_h16);
    cudaGetSymbolAddress((void**)&xbar, g_xbar);
    cudaGetSymbolAddress((void**)&w16,  g_w16);
    cudaGetSymbolAddress((void**)&cnt,  g_cnt);
    cudaGetSymbolAddress((void**)&off,  g_off);
    cudaGetSymbolAddress((void**)&cur,  g_cur);
    cudaGetSymbolAddress((void**)&bsum, g_bsum);
    cudaGetSymbolAddress((void**)&pack, g_pack);

    cudaFuncSetAttribute(gemmK_k, cudaFuncAttributeMaxDynamicSharedMemorySize, GSMEM);

    const int gemm_grid = (N + TM - 1) / TM;
    const int agg_grid  = (NN * 32 + 255) / 256;
    const int nb = (M8 + 1023) / 1024;
    const size_t n4 = (size_t)N * DD / 4;

    detect_k<<<1, 256>>>(et, E);
    zero_cnt_k<<<(M8 + 255) / 256, 256>>>(cnt);
    count_k<<<(E + 255) / 256, 256>>>(ei, et, cnt, E);
    scan1_k<<<nb, 256>>>(cnt, off, bsum, M8);
    scan2_k<<<1, 1024>>>(bsum, nb);
    scan3_k<<<(M8 + 255) / 256, 256>>>(off, cur, bsum, M8);
    scatter_k<<<(E + 255) / 256, 256>>>(ei, et, cur, pack, E);

    cvt16_k<<<(int)((n4 + 255) / 256), 256>>>(x, x16, n4);

    // Layer 1: h16 = relu( x@root1 + b1 + sum_r xbar_r@W1r )
    cvtw9_k<<<(9 * DD * DD + 255) / 256, 256>>>(root1, W1, w16);
    aggx_k<<<agg_grid, 256>>>(off, pack, x16, xbar, E);
    gemmK_k<<<gemm_grid, NTHR, GSMEM>>>(x16, xbar, w16, b1, nullptr, h16, N);

    // Layer 2: out = h@root2 + b2 + sum_r hbar_r@W2r
    cvtw9_k<<<(9 * DD * DD + 255) / 256, 256>>>(root2, W2, w16);
    aggx_k<<<agg_grid, 256>>>(off, pack, h16, xbar, E);
    gemmK_k<<<gemm_grid, NTHR, GSMEM>>>(h16, xbar, w16, b2, out, nullptr, N);
}